// round 4
// baseline (speedup 1.0000x reference)
#include <cuda_runtime.h>
#include <cuda_bf16.h>
#include <math.h>
#include <stdint.h>

// Problem constants (B=8, S=1024, D=1024)
#define BATCH 8
#define SEQ   1024
#define DIM   1024
#define NROWS (BATCH*SEQ)     // 8192
#define INV1024 (1.0f/1024.0f)

// ---------------- scratch (__device__ globals: no allocations allowed) ----------------
__device__ __nv_bfloat16 g_xbf[(size_t)NROWS*DIM];     // layernormed X, bf16   (16 MB)
__device__ __nv_bfloat16 g_wbf[(size_t)2048*DIM];      // [Wq;Wk] bf16          (4 MB)
__device__ float         g_qk[(size_t)NROWS*2048];     // [Q|K] fp32            (64 MB)
__device__ float         g_pp[NROWS];                  // p[s,s+1]
__device__ float         g_pm[NROWS];                  // p[s,s-1]
__device__ int           g_msk[NROWS];                 // row fully masked
__device__ double        g_c[NROWS];                   // exclusive prefix of log-band

// ---------------- helpers ----------------
__device__ __forceinline__ void cp_async16(void* sm, const void* gm) {
    unsigned sa = (unsigned)__cvta_generic_to_shared(sm);
    asm volatile("cp.async.cg.shared.global [%0], [%1], 16;\n" :: "r"(sa), "l"(gm) : "memory");
}
#define CP_COMMIT() asm volatile("cp.async.commit_group;\n" ::)
#define CP_WAIT(n)  asm volatile("cp.async.wait_group %0;\n" :: "n"(n))

__device__ __forceinline__ void mma16816(float* c, const uint32_t* a, const uint32_t* b) {
    asm volatile(
        "mma.sync.aligned.m16n8k16.row.col.f32.bf16.bf16.f32 "
        "{%0,%1,%2,%3}, {%4,%5,%6,%7}, {%8,%9}, {%0,%1,%2,%3};\n"
        : "+f"(c[0]), "+f"(c[1]), "+f"(c[2]), "+f"(c[3])
        : "r"(a[0]), "r"(a[1]), "r"(a[2]), "r"(a[3]), "r"(b[0]), "r"(b[1]));
}

// ---------------- K1: LayerNorm (ddof=1, eps added to std) -> bf16 ----------------
__global__ void ln_kernel(const float* __restrict__ ctx,
                          const float* __restrict__ ln_a,
                          const float* __restrict__ ln_b) {
    int r = blockIdx.x;            // 0..8191
    int tid = threadIdx.x;         // 256 threads, 4 elems each
    const float4* xrow = reinterpret_cast<const float4*>(ctx + (size_t)r * DIM);
    float4 v = xrow[tid];

    __shared__ float red[8];
    // pass 1: mean
    float s = v.x + v.y + v.z + v.w;
    #pragma unroll
    for (int o = 16; o; o >>= 1) s += __shfl_xor_sync(0xffffffffu, s, o);
    if ((tid & 31) == 0) red[tid >> 5] = s;
    __syncthreads();
    float tot = 0.f;
    #pragma unroll
    for (int i = 0; i < 8; i++) tot += red[i];
    float mean = tot * (1.0f / 1024.0f);
    __syncthreads();
    // pass 2: unbiased variance
    float dx0 = v.x - mean, dx1 = v.y - mean, dx2 = v.z - mean, dx3 = v.w - mean;
    float s2 = dx0*dx0 + dx1*dx1 + dx2*dx2 + dx3*dx3;
    #pragma unroll
    for (int o = 16; o; o >>= 1) s2 += __shfl_xor_sync(0xffffffffu, s2, o);
    if ((tid & 31) == 0) red[tid >> 5] = s2;
    __syncthreads();
    float tot2 = 0.f;
    #pragma unroll
    for (int i = 0; i < 8; i++) tot2 += red[i];
    float var = tot2 * (1.0f / 1023.0f);
    float rs = 1.0f / (sqrtf(var) + 1e-6f);

    float4 a4 = reinterpret_cast<const float4*>(ln_a)[tid];
    float4 b4 = reinterpret_cast<const float4*>(ln_b)[tid];
    float y0 = a4.x * (dx0 * rs) + b4.x;
    float y1 = a4.y * (dx1 * rs) + b4.y;
    float y2 = a4.z * (dx2 * rs) + b4.z;
    float y3 = a4.w * (dx3 * rs) + b4.w;

    __nv_bfloat162* orow = reinterpret_cast<__nv_bfloat162*>(g_xbf + (size_t)r * DIM);
    orow[tid*2]   = __floats2bfloat162_rn(y0, y1);
    orow[tid*2+1] = __floats2bfloat162_rn(y2, y3);
}

// ---------------- K2: convert weights to bf16, concatenated [Wq;Wk] ----------------
__global__ void wconv_kernel(const float* __restrict__ Wq, const float* __restrict__ Wk) {
    int idx = blockIdx.x * blockDim.x + threadIdx.x;   // 0..524287, 4 elems each
    int e = idx * 4;
    const float* src = (e < DIM*DIM) ? (Wq + e) : (Wk + (e - DIM*DIM));
    float4 w = *reinterpret_cast<const float4*>(src);
    __nv_bfloat162* dst = reinterpret_cast<__nv_bfloat162*>(g_wbf + e);
    dst[0] = __floats2bfloat162_rn(w.x, w.y);
    dst[1] = __floats2bfloat162_rn(w.z, w.w);
}

// ---------------- K3: GEMM  C[8192,2048] = Xbf[8192,1024] * Wbf[2048,1024]^T ----------------
#define GBM 128
#define GBN 128
#define GBK 32
#define SPAD 40   // padded row stride (bf16 elems) => conflict-free 32b smem fragment loads

__global__ __launch_bounds__(256, 2) void gemm_kernel() {
    __shared__ __align__(16) __nv_bfloat16 As[2][GBM][SPAD];
    __shared__ __align__(16) __nv_bfloat16 Bs[2][GBN][SPAD];

    int tid  = threadIdx.x;
    int m0   = blockIdx.y * GBM;
    int n0   = blockIdx.x * GBN;
    int warp = tid >> 5, lane = tid & 31;
    int wm = warp >> 2, wn = warp & 3;      // warp grid 2 (M) x 4 (N); warp tile 64x32
    int gid = lane >> 2, tig = lane & 3;

    float acc[4][4][4];
    #pragma unroll
    for (int a = 0; a < 4; a++)
        #pragma unroll
        for (int b = 0; b < 4; b++)
            #pragma unroll
            for (int c = 0; c < 4; c++) acc[a][b][c] = 0.f;

    const __nv_bfloat16* Ag = g_xbf;
    const __nv_bfloat16* Bg = g_wbf;

    auto load_stage = [&](int buf, int kt) {
        int k0 = kt * GBK;
        #pragma unroll
        for (int h = 0; h < 2; h++) {
            int chunk = tid + h * 256;       // 512 chunks of 16B per operand
            int row = chunk >> 2;
            int cc  = chunk & 3;
            cp_async16(&As[buf][row][cc*8], Ag + (size_t)(m0 + row) * DIM + k0 + cc*8);
            cp_async16(&Bs[buf][row][cc*8], Bg + (size_t)(n0 + row) * DIM + k0 + cc*8);
        }
        CP_COMMIT();
    };

    const int NT = DIM / GBK;   // 32
    load_stage(0, 0);

    for (int kt = 0; kt < NT; kt++) {
        int buf = kt & 1;
        if (kt + 1 < NT) { load_stage(buf ^ 1, kt + 1); CP_WAIT(1); }
        else             { CP_WAIT(0); }
        __syncthreads();

        #pragma unroll
        for (int ks = 0; ks < 2; ks++) {
            int col = ks * 16 + tig * 2;
            uint32_t af[4][4], bfr[4][2];
            #pragma unroll
            for (int mt = 0; mt < 4; mt++) {
                int arow = wm * 64 + mt * 16 + gid;
                af[mt][0] = *reinterpret_cast<const uint32_t*>(&As[buf][arow    ][col    ]);
                af[mt][1] = *reinterpret_cast<const uint32_t*>(&As[buf][arow + 8][col    ]);
                af[mt][2] = *reinterpret_cast<const uint32_t*>(&As[buf][arow    ][col + 8]);
                af[mt][3] = *reinterpret_cast<const uint32_t*>(&As[buf][arow + 8][col + 8]);
            }
            #pragma unroll
            for (int nt = 0; nt < 4; nt++) {
                int brow = wn * 32 + nt * 8 + gid;
                bfr[nt][0] = *reinterpret_cast<const uint32_t*>(&Bs[buf][brow][col    ]);
                bfr[nt][1] = *reinterpret_cast<const uint32_t*>(&Bs[buf][brow][col + 8]);
            }
            #pragma unroll
            for (int mt = 0; mt < 4; mt++)
                #pragma unroll
                for (int nt = 0; nt < 4; nt++)
                    mma16816(acc[mt][nt], af[mt], bfr[nt]);
        }
        __syncthreads();
    }

    #pragma unroll
    for (int mt = 0; mt < 4; mt++) {
        int row0 = m0 + wm * 64 + mt * 16 + gid;
        #pragma unroll
        for (int nt = 0; nt < 4; nt++) {
            int coln = n0 + wn * 32 + nt * 8 + tig * 2;
            *reinterpret_cast<float2*>(&g_qk[(size_t)row0 * 2048 + coln]) =
                make_float2(acc[mt][nt][0], acc[mt][nt][1]);
            *reinterpret_cast<float2*>(&g_qk[(size_t)(row0 + 8) * 2048 + coln]) =
                make_float2(acc[mt][nt][2], acc[mt][nt][3]);
        }
    }
}

// ---------------- K4: band scores + 2-way softmax -> p_plus/p_minus/rowmask ----------------
__global__ void band_kernel(const int* __restrict__ eos,
                            const float* __restrict__ bq,
                            const float* __restrict__ bk) {
    int r = blockIdx.x * 8 + (threadIdx.x >> 5);   // 8192 warps, one row each
    int lane = threadIdx.x & 31;
    int b = r >> 10, s = r & 1023;

    // band validity: t = s+1 / s-1 must exist AND eos_mask bit set (mask = eos & band(=1))
    int ep = 0, em = 0;
    if (lane == 0) {
        if (s < SEQ - 1) ep = eos[((size_t)b * SEQ + s) * SEQ + (s + 1)] & 1;
        if (s > 0)       em = eos[((size_t)b * SEQ + s) * SEQ + (s - 1)] & 1;
    }
    ep = __shfl_sync(0xffffffffu, ep, 0);
    em = __shfl_sync(0xffffffffu, em, 0);
    bool vp = (ep != 0), vm = (em != 0);

    float accp = 0.f, accm = 0.f;
    if (vp || vm) {
        const float2* q2  = reinterpret_cast<const float2*>(g_qk + (size_t)r * 2048);
        const float2* kp2 = reinterpret_cast<const float2*>(g_qk + (size_t)(r + 1) * 2048 + 1024);
        const float2* km2 = reinterpret_cast<const float2*>(g_qk + (size_t)(r - 1) * 2048 + 1024);
        const float2* bq2 = reinterpret_cast<const float2*>(bq);
        const float2* bk2 = reinterpret_cast<const float2*>(bk);
        #pragma unroll
        for (int i = 0; i < 16; i++) {
            int d = lane + i * 32;
            float2 qf = q2[d];
            float2 qb = bq2[d];
            qf.x += qb.x; qf.y += qb.y;
            float2 kb = bk2[d];
            if (vp) { float2 kf = kp2[d]; accp += qf.x * (kf.x + kb.x) + qf.y * (kf.y + kb.y); }
            if (vm) { float2 kf = km2[d]; accm += qf.x * (kf.x + kb.x) + qf.y * (kf.y + kb.y); }
        }
        #pragma unroll
        for (int o = 16; o; o >>= 1) {
            accp += __shfl_xor_sync(0xffffffffu, accp, o);
            accm += __shfl_xor_sync(0xffffffffu, accm, o);
        }
    }

    if (lane == 0) {
        float pp = 0.f, pm = 0.f;
        int mk = 0;
        if (!vp && !vm) {
            mk = 1;   // fully masked row -> uniform 1/1024 handled downstream
        } else {
            float sp = vp ? accp * (1.0f / 1024.0f) : -INFINITY;
            float sm = vm ? accm * (1.0f / 1024.0f) : -INFINITY;
            float mx = fmaxf(sp, sm);
            float e1 = vp ? expf(sp - mx) : 0.f;
            float e2 = vm ? expf(sm - mx) : 0.f;
            float z = e1 + e2;
            pp = e1 / z; pm = e2 / z;
        }
        g_pp[r] = pp; g_pm[r] = pm; g_msk[r] = mk;
    }
}

// ---------------- K5: per-batch fp64 exclusive prefix scan of log(neibor band) ----------------
__global__ void scan_kernel() {
    int b = blockIdx.x;
    int s = threadIdx.x;          // 1024 threads
    int r = b * SEQ + s;
    __shared__ double sd[SEQ];

    double logn = 0.0;
    if (s < SEQ - 1) {
        float Pp = g_msk[r]     ? INV1024 : g_pp[r];
        float Pm = g_msk[r + 1] ? INV1024 : g_pm[r + 1];
        float nb = sqrtf(Pp * Pm + 1e-9f);
        logn = (double)logf(nb + 1e-9f);
    }
    sd[s] = logn;
    __syncthreads();
    for (int off = 1; off < SEQ; off <<= 1) {
        double v = (s >= off) ? sd[s - off] : 0.0;
        __syncthreads();
        sd[s] += v;
        __syncthreads();
    }
    g_c[r] = (s == 0) ? 0.0 : sd[s - 1];
}

// ---------------- K6: assemble g and neibor, write both outputs ----------------
__global__ void out_kernel(float* __restrict__ out) {
    int b  = blockIdx.y;
    int s0 = blockIdx.x * 16;
    int tid = threadIdx.x;         // 256 threads, 4 t-values each

    __shared__ double c_sh[SEQ];
    __shared__ float  pp_sh[SEQ];
    __shared__ float  pm_sh[SEQ];
    __shared__ unsigned char mk_sh[SEQ];

    int base = b * SEQ;
    for (int i = tid; i < SEQ; i += 256) {
        c_sh[i]  = g_c[base + i];
        pp_sh[i] = g_pp[base + i];
        pm_sh[i] = g_pm[base + i];
        mk_sh[i] = (unsigned char)g_msk[base + i];
    }
    __syncthreads();

    float* gout = out;
    float* nout = out + (size_t)BATCH * SEQ * SEQ;
    int t0 = tid * 4;

    for (int i = 0; i < 16; i++) {
        int s = s0 + i;
        double cs = c_sh[s];
        float pps = pp_sh[s], pms = pm_sh[s];
        int ms = mk_sh[s];
        float4 gg, nn;
        float* gp = reinterpret_cast<float*>(&gg);
        float* np = reinterpret_cast<float*>(&nn);
        #pragma unroll
        for (int j = 0; j < 4; j++) {
            int t = t0 + j;
            int mt = mk_sh[t];
            // P(s,t) and P(t,s) from compact softmax representation
            float Pst = ms ? INV1024 : ((t == s + 1) ? pps : ((t == s - 1) ? pms : 0.f));
            float Pts = mt ? INV1024 : ((t == s - 1) ? pp_sh[t] : ((t == s + 1) ? pm_sh[t] : 0.f));
            float nb = sqrtf(Pst * Pts + 1e-9f);
            np[j] = nb;
            float gv;
            if (t == s) {
                gv = nb;                                   // diag: neibor[s,s]
            } else {
                double d = (t > s) ? (c_sh[t] - cs) : (cs - c_sh[t]);
                gv = expf((float)d) + 1e-9f;               // off-diag: exp(telescoped sum)+1e-9
            }
            gp[j] = gv;
        }
        size_t o = ((size_t)(base + s)) * SEQ + t0;
        *reinterpret_cast<float4*>(gout + o) = gg;
        *reinterpret_cast<float4*>(nout + o) = nn;
    }
}

// ---------------- launch ----------------
extern "C" void kernel_launch(void* const* d_in, const int* in_sizes, int n_in,
                              void* d_out, int out_size) {
    const float* context = (const float*)d_in[0];
    const int*   eos     = (const int*)  d_in[1];
    const float* Wq      = (const float*)d_in[2];
    const float* bq      = (const float*)d_in[3];
    const float* Wk      = (const float*)d_in[4];
    const float* bk      = (const float*)d_in[5];
    const float* ln_a    = (const float*)d_in[6];
    const float* ln_b    = (const float*)d_in[7];
    float* out = (float*)d_out;

    ln_kernel<<<NROWS, 256>>>(context, ln_a, ln_b);
    wconv_kernel<<<2048, 256>>>(Wq, Wk);
    gemm_kernel<<<dim3(2048 / GBN, NROWS / GBM), 256>>>();
    band_kernel<<<NROWS / 8, 256>>>(eos, bq, bk);
    scan_kernel<<<BATCH, SEQ>>>();
    out_kernel<<<dim3(SEQ / 16, BATCH), 256>>>(out);
}

// round 5
// speedup vs baseline: 1.0896x; 1.0896x over previous
#include <cuda_runtime.h>
#include <cuda_bf16.h>
#include <math.h>
#include <stdint.h>

// Problem constants (B=8, S=1024, D=1024)
#define BATCH 8
#define SEQ   1024
#define DIM   1024
#define NROWS (BATCH*SEQ)     // 8192
#define INV1024 (1.0f/1024.0f)

// ---------------- scratch (__device__ globals: no allocations allowed) ----------------
__device__ __nv_bfloat16 g_xbf[(size_t)NROWS*DIM];     // layernormed X, bf16   (16 MB)
__device__ __nv_bfloat16 g_wqt[(size_t)DIM*DIM];       // Wq transposed [i][o]  (2 MB)
__device__ __nv_bfloat16 g_wkt[(size_t)DIM*DIM];       // Wk transposed [j][o]  (2 MB)
__device__ __nv_bfloat16 g_mt [(size_t)DIM*DIM];       // Mt[j][i] = (Wq^T Wk)[i][j] (2 MB)
__device__ float         g_y  [(size_t)NROWS*DIM];     // y = X * M, fp32       (32 MB)
__device__ float         g_ub[DIM];                    // Wq^T bk
__device__ float         g_vb[DIM];                    // Wk^T bq
__device__ float         g_cdot;                       // bq . bk
__device__ float         g_pp[NROWS];                  // p[s,s+1]
__device__ float         g_pm[NROWS];                  // p[s,s-1]
__device__ int           g_msk[NROWS];                 // row fully masked
__device__ double        g_c[NROWS];                   // exclusive prefix of log-band

// ---------------- helpers ----------------
__device__ __forceinline__ void cp_async16(void* sm, const void* gm) {
    unsigned sa = (unsigned)__cvta_generic_to_shared(sm);
    asm volatile("cp.async.cg.shared.global [%0], [%1], 16;\n" :: "r"(sa), "l"(gm) : "memory");
}
#define CP_COMMIT() asm volatile("cp.async.commit_group;\n" ::)
#define CP_WAIT(n)  asm volatile("cp.async.wait_group %0;\n" :: "n"(n))

__device__ __forceinline__ void mma16816(float* c, const uint32_t* a, const uint32_t* b) {
    asm volatile(
        "mma.sync.aligned.m16n8k16.row.col.f32.bf16.bf16.f32 "
        "{%0,%1,%2,%3}, {%4,%5,%6,%7}, {%8,%9}, {%0,%1,%2,%3};\n"
        : "+f"(c[0]), "+f"(c[1]), "+f"(c[2]), "+f"(c[3])
        : "r"(a[0]), "r"(a[1]), "r"(a[2]), "r"(a[3]), "r"(b[0]), "r"(b[1]));
}

// ---------------- K1: LayerNorm (ddof=1, eps added to std) -> bf16 ----------------
__global__ void ln_kernel(const float* __restrict__ ctx,
                          const float* __restrict__ ln_a,
                          const float* __restrict__ ln_b) {
    int r = blockIdx.x;            // 0..8191
    int tid = threadIdx.x;         // 256 threads, 4 elems each
    const float4* xrow = reinterpret_cast<const float4*>(ctx + (size_t)r * DIM);
    float4 v = xrow[tid];

    __shared__ float red[8];
    float s = v.x + v.y + v.z + v.w;
    #pragma unroll
    for (int o = 16; o; o >>= 1) s += __shfl_xor_sync(0xffffffffu, s, o);
    if ((tid & 31) == 0) red[tid >> 5] = s;
    __syncthreads();
    float tot = 0.f;
    #pragma unroll
    for (int i = 0; i < 8; i++) tot += red[i];
    float mean = tot * (1.0f / 1024.0f);
    __syncthreads();
    float dx0 = v.x - mean, dx1 = v.y - mean, dx2 = v.z - mean, dx3 = v.w - mean;
    float s2 = dx0*dx0 + dx1*dx1 + dx2*dx2 + dx3*dx3;
    #pragma unroll
    for (int o = 16; o; o >>= 1) s2 += __shfl_xor_sync(0xffffffffu, s2, o);
    if ((tid & 31) == 0) red[tid >> 5] = s2;
    __syncthreads();
    float tot2 = 0.f;
    #pragma unroll
    for (int i = 0; i < 8; i++) tot2 += red[i];
    float var = tot2 * (1.0f / 1023.0f);
    float rs = 1.0f / (sqrtf(var) + 1e-6f);

    float4 a4 = reinterpret_cast<const float4*>(ln_a)[tid];
    float4 b4 = reinterpret_cast<const float4*>(ln_b)[tid];
    float y0 = a4.x * (dx0 * rs) + b4.x;
    float y1 = a4.y * (dx1 * rs) + b4.y;
    float y2 = a4.z * (dx2 * rs) + b4.z;
    float y3 = a4.w * (dx3 * rs) + b4.w;

    __nv_bfloat162* orow = reinterpret_cast<__nv_bfloat162*>(g_xbf + (size_t)r * DIM);
    orow[tid*2]   = __floats2bfloat162_rn(y0, y1);
    orow[tid*2+1] = __floats2bfloat162_rn(y2, y3);
}

// ---------------- K2: transpose+convert Wq,Wk -> bf16 [in][out] layout ----------------
__global__ void tconv_kernel(const float* __restrict__ Wq, const float* __restrict__ Wk) {
    __shared__ float t[32][33];
    int i0 = blockIdx.x * 32;
    int o0 = blockIdx.y * 32;
    const float* src = blockIdx.z ? Wk : Wq;
    __nv_bfloat16* dst = blockIdx.z ? g_wkt : g_wqt;
    int c = threadIdx.x & 31, r = threadIdx.x >> 5;   // 8 rows/iter
    #pragma unroll
    for (int rr = 0; rr < 4; rr++) {
        int row = rr * 8 + r;
        t[row][c] = src[(size_t)(o0 + row) * DIM + i0 + c];
    }
    __syncthreads();
    #pragma unroll
    for (int rr = 0; rr < 4; rr++) {
        int row = rr * 8 + r;
        dst[(size_t)(i0 + row) * DIM + o0 + c] = __float2bfloat16(t[c][row]);
    }
}

// ---------------- K3: templated 3-stage bf16 GEMM (C[m,n] = sum_k A[m,k]*B[n,k]) --------
// MODE 0: Mt[j,i] = sum_o Wkt[j,o]*Wqt[i,o]   (grid 8x8,  out bf16 g_mt)
// MODE 1: y[s,j]  = sum_i Xbf[s,i]*Mt[j,i]    (grid 8x64, out f32  g_y)
#define GBM 128
#define GBN 128
#define GBK 32
#define SPAD 40
#define GSTAGES 3
#define SMEMSZ (GSTAGES * (GBM + GBN) * SPAD * 2)

template <int MODE>
__global__ __launch_bounds__(256, 2) void gemm_tpl() {
    extern __shared__ __align__(16) char dynsm[];
    auto As = reinterpret_cast<__nv_bfloat16(*)[GBM][SPAD]>(dynsm);
    auto Bs = reinterpret_cast<__nv_bfloat16(*)[GBN][SPAD]>(dynsm + GSTAGES * GBM * SPAD * 2);

    const __nv_bfloat16* Ag = (MODE == 0) ? g_wkt : g_xbf;
    const __nv_bfloat16* Bg = (MODE == 0) ? g_wqt : g_mt;
    const int N = DIM;   // output col count / stride (1024 both modes)

    int tid  = threadIdx.x;
    int m0   = blockIdx.y * GBM;
    int n0   = blockIdx.x * GBN;
    int warp = tid >> 5, lane = tid & 31;
    int wm = warp >> 2, wn = warp & 3;      // 2 (M) x 4 (N) warps; warp tile 64x32
    int gid = lane >> 2, tig = lane & 3;

    float acc[4][4][4];
    #pragma unroll
    for (int a = 0; a < 4; a++)
        #pragma unroll
        for (int b = 0; b < 4; b++)
            #pragma unroll
            for (int c = 0; c < 4; c++) acc[a][b][c] = 0.f;

    auto load_stage = [&](int buf, int kt) {
        int k0 = kt * GBK;
        #pragma unroll
        for (int h = 0; h < 2; h++) {
            int chunk = tid + h * 256;       // 512 chunks of 16B per operand
            int row = chunk >> 2;
            int cc  = chunk & 3;
            cp_async16(&As[buf][row][cc*8], Ag + (size_t)(m0 + row) * DIM + k0 + cc*8);
            cp_async16(&Bs[buf][row][cc*8], Bg + (size_t)(n0 + row) * DIM + k0 + cc*8);
        }
        CP_COMMIT();
    };

    const int NT = DIM / GBK;   // 32
    load_stage(0, 0);
    load_stage(1, 1);

    for (int kt = 0; kt < NT; kt++) {
        if (kt < NT - 1) { CP_WAIT(1); } else { CP_WAIT(0); }
        __syncthreads();
        if (kt + 2 < NT) load_stage((kt + 2) % GSTAGES, kt + 2);
        int buf = kt % GSTAGES;

        #pragma unroll
        for (int ks = 0; ks < 2; ks++) {
            int col = ks * 16 + tig * 2;
            uint32_t af[4][4], bfr[4][2];
            #pragma unroll
            for (int mt = 0; mt < 4; mt++) {
                int arow = wm * 64 + mt * 16 + gid;
                af[mt][0] = *reinterpret_cast<const uint32_t*>(&As[buf][arow    ][col    ]);
                af[mt][1] = *reinterpret_cast<const uint32_t*>(&As[buf][arow + 8][col    ]);
                af[mt][2] = *reinterpret_cast<const uint32_t*>(&As[buf][arow    ][col + 8]);
                af[mt][3] = *reinterpret_cast<const uint32_t*>(&As[buf][arow + 8][col + 8]);
            }
            #pragma unroll
            for (int nt = 0; nt < 4; nt++) {
                int brow = wn * 32 + nt * 8 + gid;
                bfr[nt][0] = *reinterpret_cast<const uint32_t*>(&Bs[buf][brow][col    ]);
                bfr[nt][1] = *reinterpret_cast<const uint32_t*>(&Bs[buf][brow][col + 8]);
            }
            #pragma unroll
            for (int mt = 0; mt < 4; mt++)
                #pragma unroll
                for (int nt = 0; nt < 4; nt++)
                    mma16816(acc[mt][nt], af[mt], bfr[nt]);
        }
    }

    #pragma unroll
    for (int mt = 0; mt < 4; mt++) {
        int row0 = m0 + wm * 64 + mt * 16 + gid;
        #pragma unroll
        for (int nt = 0; nt < 4; nt++) {
            int coln = n0 + wn * 32 + nt * 8 + tig * 2;
            if (MODE == 0) {
                *reinterpret_cast<__nv_bfloat162*>(&g_mt[(size_t)row0 * N + coln]) =
                    __floats2bfloat162_rn(acc[mt][nt][0], acc[mt][nt][1]);
                *reinterpret_cast<__nv_bfloat162*>(&g_mt[(size_t)(row0 + 8) * N + coln]) =
                    __floats2bfloat162_rn(acc[mt][nt][2], acc[mt][nt][3]);
            } else {
                *reinterpret_cast<float2*>(&g_y[(size_t)row0 * N + coln]) =
                    make_float2(acc[mt][nt][0], acc[mt][nt][1]);
                *reinterpret_cast<float2*>(&g_y[(size_t)(row0 + 8) * N + coln]) =
                    make_float2(acc[mt][nt][2], acc[mt][nt][3]);
            }
        }
    }
}

// ---------------- K4: bias vectors ub = Wq^T bk, vb = Wk^T bq, cdot = bq.bk ----------------
__global__ void bias_kernel(const float* __restrict__ bq, const float* __restrict__ bk) {
    int i    = blockIdx.x * 8 + (threadIdx.x >> 5);
    int lane = threadIdx.x & 31;
    float su = 0.f, sv = 0.f;
    #pragma unroll 4
    for (int j = 0; j < 32; j++) {
        int o = lane + j * 32;
        su += __bfloat162float(g_wqt[(size_t)i * DIM + o]) * bk[o];
        sv += __bfloat162float(g_wkt[(size_t)i * DIM + o]) * bq[o];
    }
    #pragma unroll
    for (int o = 16; o; o >>= 1) {
        su += __shfl_xor_sync(0xffffffffu, su, o);
        sv += __shfl_xor_sync(0xffffffffu, sv, o);
    }
    if (lane == 0) { g_ub[i] = su; g_vb[i] = sv; }
    if (blockIdx.x == 0 && threadIdx.x < 32) {
        float sc = 0.f;
        for (int j = 0; j < 32; j++) { int o = lane + j * 32; sc += bq[o] * bk[o]; }
        #pragma unroll
        for (int o = 16; o; o >>= 1) sc += __shfl_xor_sync(0xffffffffu, sc, o);
        if (lane == 0) g_cdot = sc;
    }
}

// ---------------- K5: band scores + 2-way softmax -> p_plus/p_minus/rowmask ----------------
__global__ void band_kernel(const int* __restrict__ eos) {
    int r = blockIdx.x * 8 + (threadIdx.x >> 5);   // one warp per row
    int lane = threadIdx.x & 31;
    int b = r >> 10, s = r & 1023;

    int ep = 0, em = 0;
    if (lane == 0) {
        if (s < SEQ - 1) ep = eos[((size_t)b * SEQ + s) * SEQ + (s + 1)];
        if (s > 0)       em = eos[((size_t)b * SEQ + s) * SEQ + (s - 1)];
    }
    ep = __shfl_sync(0xffffffffu, ep, 0);
    em = __shfl_sync(0xffffffffu, em, 0);
    bool vp = (ep != 0), vm = (em != 0);

    int rp = (r == NROWS - 1) ? r : r + 1;
    int rm = (r == 0) ? r : r - 1;

    const float2*         y2  = reinterpret_cast<const float2*>(g_y + (size_t)r * DIM);
    const __nv_bfloat162* xp2 = reinterpret_cast<const __nv_bfloat162*>(g_xbf + (size_t)rp * DIM);
    const __nv_bfloat162* xm2 = reinterpret_cast<const __nv_bfloat162*>(g_xbf + (size_t)rm * DIM);
    const __nv_bfloat162* xs2 = reinterpret_cast<const __nv_bfloat162*>(g_xbf + (size_t)r * DIM);
    const float2*         ub2 = reinterpret_cast<const float2*>(g_ub);
    const float2*         vb2 = reinterpret_cast<const float2*>(g_vb);

    float dotp = 0.f, dotm = 0.f, as_ = 0.f, bp_ = 0.f, bm_ = 0.f;
    #pragma unroll
    for (int i = 0; i < 16; i++) {
        int d = lane + i * 32;
        float2 y  = y2[d];
        float2 xp = __bfloat1622float2(xp2[d]);
        float2 xm = __bfloat1622float2(xm2[d]);
        float2 xs = __bfloat1622float2(xs2[d]);
        float2 ub = ub2[d];
        float2 vb = vb2[d];
        dotp += y.x * xp.x + y.y * xp.y;
        dotm += y.x * xm.x + y.y * xm.y;
        as_  += xs.x * ub.x + xs.y * ub.y;
        bp_  += xp.x * vb.x + xp.y * vb.y;
        bm_  += xm.x * vb.x + xm.y * vb.y;
    }
    #pragma unroll
    for (int o = 16; o; o >>= 1) {
        dotp += __shfl_xor_sync(0xffffffffu, dotp, o);
        dotm += __shfl_xor_sync(0xffffffffu, dotm, o);
        as_  += __shfl_xor_sync(0xffffffffu, as_,  o);
        bp_  += __shfl_xor_sync(0xffffffffu, bp_,  o);
        bm_  += __shfl_xor_sync(0xffffffffu, bm_,  o);
    }

    if (lane == 0) {
        float pp = 0.f, pm = 0.f;
        int mk = 0;
        if (!vp && !vm) {
            mk = 1;   // fully masked row -> uniform 1/1024 downstream
        } else {
            float cd = g_cdot;
            float sp = vp ? (dotp + as_ + bp_ + cd) * INV1024 : -INFINITY;
            float sm = vm ? (dotm + as_ + bm_ + cd) * INV1024 : -INFINITY;
            float mx = fmaxf(sp, sm);
            float e1 = vp ? expf(sp - mx) : 0.f;
            float e2 = vm ? expf(sm - mx) : 0.f;
            float z = e1 + e2;
            pp = e1 / z; pm = e2 / z;
        }
        g_pp[r] = pp; g_pm[r] = pm; g_msk[r] = mk;
    }
}

// ---------------- K6: per-batch fp64 exclusive prefix scan of log(neibor band) ----------------
__global__ void scan_kernel() {
    int b = blockIdx.x;
    int s = threadIdx.x;          // 1024 threads
    int r = b * SEQ + s;
    __shared__ double sd[SEQ];

    double logn = 0.0;
    if (s < SEQ - 1) {
        float Pp = g_msk[r]     ? INV1024 : g_pp[r];
        float Pm = g_msk[r + 1] ? INV1024 : g_pm[r + 1];
        float nb = sqrtf(Pp * Pm + 1e-9f);
        logn = (double)logf(nb + 1e-9f);
    }
    sd[s] = logn;
    __syncthreads();
    for (int off = 1; off < SEQ; off <<= 1) {
        double v = (s >= off) ? sd[s - off] : 0.0;
        __syncthreads();
        sd[s] += v;
        __syncthreads();
    }
    g_c[r] = (s == 0) ? 0.0 : sd[s - 1];
}

// ---------------- K7: assemble g and neibor, write both outputs ----------------
__global__ void out_kernel(float* __restrict__ out) {
    int b  = blockIdx.y;
    int s0 = blockIdx.x * 16;
    int tid = threadIdx.x;         // 256 threads, 4 t-values each

    __shared__ double c_sh[SEQ];
    __shared__ float  pp_sh[SEQ];
    __shared__ float  pm_sh[SEQ];
    __shared__ unsigned char mk_sh[SEQ];

    int base = b * SEQ;
    for (int i = tid; i < SEQ; i += 256) {
        c_sh[i]  = g_c[base + i];
        pp_sh[i] = g_pp[base + i];
        pm_sh[i] = g_pm[base + i];
        mk_sh[i] = (unsigned char)g_msk[base + i];
    }
    __syncthreads();

    float* gout = out;
    float* nout = out + (size_t)BATCH * SEQ * SEQ;
    int t0 = tid * 4;

    for (int i = 0; i < 16; i++) {
        int s = s0 + i;
        double cs = c_sh[s];
        float pps = pp_sh[s], pms = pm_sh[s];
        int ms = mk_sh[s];
        float4 gg, nn;
        float* gp = reinterpret_cast<float*>(&gg);
        float* np = reinterpret_cast<float*>(&nn);
        #pragma unroll
        for (int j = 0; j < 4; j++) {
            int t = t0 + j;
            int mt = mk_sh[t];
            float Pst = ms ? INV1024 : ((t == s + 1) ? pps : ((t == s - 1) ? pms : 0.f));
            float Pts = mt ? INV1024 : ((t == s - 1) ? pp_sh[t] : ((t == s + 1) ? pm_sh[t] : 0.f));
            float nb = sqrtf(Pst * Pts + 1e-9f);
            np[j] = nb;
            float gv;
            if (t == s) {
                gv = nb;                                   // diag: neibor[s,s]
            } else {
                double d = (t > s) ? (c_sh[t] - cs) : (cs - c_sh[t]);
                gv = expf((float)d) + 1e-9f;               // off-diag: telescoped product
            }
            gp[j] = gv;
        }
        size_t o = ((size_t)(base + s)) * SEQ + t0;
        *reinterpret_cast<float4*>(gout + o) = gg;
        *reinterpret_cast<float4*>(nout + o) = nn;
    }
}

// ---------------- launch ----------------
extern "C" void kernel_launch(void* const* d_in, const int* in_sizes, int n_in,
                              void* d_out, int out_size) {
    const float* context = (const float*)d_in[0];
    const int*   eos     = (const int*)  d_in[1];
    const float* Wq      = (const float*)d_in[2];
    const float* bq      = (const float*)d_in[3];
    const float* Wk      = (const float*)d_in[4];
    const float* bk      = (const float*)d_in[5];
    const float* ln_a    = (const float*)d_in[6];
    const float* ln_b    = (const float*)d_in[7];
    float* out = (float*)d_out;

    // opt-in to >48KB dynamic smem (idempotent; also set on the pre-capture call)
    cudaFuncSetAttribute(gemm_tpl<0>, cudaFuncAttributeMaxDynamicSharedMemorySize, SMEMSZ);
    cudaFuncSetAttribute(gemm_tpl<1>, cudaFuncAttributeMaxDynamicSharedMemorySize, SMEMSZ);

    ln_kernel<<<NROWS, 256>>>(context, ln_a, ln_b);
    tconv_kernel<<<dim3(32, 32, 2), 256>>>(Wq, Wk);
    gemm_tpl<0><<<dim3(DIM / GBN, DIM / GBM), 256, SMEMSZ>>>();      // Mt = Wk^T Wq
    bias_kernel<<<128, 256>>>(bq, bk);
    gemm_tpl<1><<<dim3(DIM / GBN, NROWS / GBM), 256, SMEMSZ>>>();    // y = X * M
    band_kernel<<<NROWS / 8, 256>>>(eos);
    scan_kernel<<<BATCH, SEQ>>>();
    out_kernel<<<dim3(SEQ / 16, BATCH), 256>>>(out);
}

// round 7
// speedup vs baseline: 1.3443x; 1.2338x over previous
#include <cuda_runtime.h>
#include <cuda_bf16.h>
#include <math.h>
#include <stdint.h>

// Problem constants (B=8, S=1024, D=1024)
#define BATCH 8
#define SEQ   1024
#define DIM   1024
#define NROWS (BATCH*SEQ)     // 8192
#define INV1024 (1.0f/1024.0f)

// ---------------- scratch (__device__ globals: no allocations allowed) ----------------
__device__ __nv_bfloat16 g_xbf[(size_t)NROWS*DIM];     // layernormed X, bf16   (16 MB)
__device__ __nv_bfloat16 g_wqt[(size_t)DIM*DIM];       // Wq transposed [i][o]  (2 MB)
__device__ __nv_bfloat16 g_wkt[(size_t)DIM*DIM];       // Wk transposed [j][o]  (2 MB)
__device__ __nv_bfloat16 g_mt [(size_t)DIM*DIM];       // Mt[j][i] = (Wq^T Wk)[i][j] (2 MB)
__device__ __nv_bfloat16 g_ybf[(size_t)NROWS*DIM];     // y = X * M, bf16       (16 MB)
__device__ float         g_ub[DIM];                    // Wq^T bk
__device__ float         g_vb[DIM];                    // Wk^T bq
__device__ float         g_cdot;                       // bq . bk
__device__ float         g_pp[NROWS];                  // p[s,s+1]
__device__ float         g_pm[NROWS];                  // p[s,s-1]
__device__ int           g_msk[NROWS];                 // row fully masked
__device__ float         g_chi[NROWS];                 // prefix sum hi (fp32)
__device__ float         g_clo[NROWS];                 // prefix sum lo (fp32)

// ---------------- helpers ----------------
__device__ __forceinline__ void cp_async16(void* sm, const void* gm) {
    unsigned sa = (unsigned)__cvta_generic_to_shared(sm);
    asm volatile("cp.async.cg.shared.global [%0], [%1], 16;\n" :: "r"(sa), "l"(gm) : "memory");
}
#define CP_COMMIT() asm volatile("cp.async.commit_group;\n" ::)
#define CP_WAIT(n)  asm volatile("cp.async.wait_group %0;\n" :: "n"(n))

__device__ __forceinline__ void mma16816(float* c, const uint32_t* a, const uint32_t* b) {
    asm volatile(
        "mma.sync.aligned.m16n8k16.row.col.f32.bf16.bf16.f32 "
        "{%0,%1,%2,%3}, {%4,%5,%6,%7}, {%8,%9}, {%0,%1,%2,%3};\n"
        : "+f"(c[0]), "+f"(c[1]), "+f"(c[2]), "+f"(c[3])
        : "r"(a[0]), "r"(a[1]), "r"(a[2]), "r"(a[3]), "r"(b[0]), "r"(b[1]));
}

// ---------------- K1: LayerNorm (ddof=1, eps added to std) -> bf16 ----------------
__global__ void ln_kernel(const float* __restrict__ ctx,
                          const float* __restrict__ ln_a,
                          const float* __restrict__ ln_b) {
    int r = blockIdx.x;            // 0..8191
    int tid = threadIdx.x;         // 256 threads, 4 elems each
    const float4* xrow = reinterpret_cast<const float4*>(ctx + (size_t)r * DIM);
    float4 v = xrow[tid];

    __shared__ float red[8];
    float s = v.x + v.y + v.z + v.w;
    #pragma unroll
    for (int o = 16; o; o >>= 1) s += __shfl_xor_sync(0xffffffffu, s, o);
    if ((tid & 31) == 0) red[tid >> 5] = s;
    __syncthreads();
    float tot = 0.f;
    #pragma unroll
    for (int i = 0; i < 8; i++) tot += red[i];
    float mean = tot * (1.0f / 1024.0f);
    __syncthreads();
    float dx0 = v.x - mean, dx1 = v.y - mean, dx2 = v.z - mean, dx3 = v.w - mean;
    float s2 = dx0*dx0 + dx1*dx1 + dx2*dx2 + dx3*dx3;
    #pragma unroll
    for (int o = 16; o; o >>= 1) s2 += __shfl_xor_sync(0xffffffffu, s2, o);
    if ((tid & 31) == 0) red[tid >> 5] = s2;
    __syncthreads();
    float tot2 = 0.f;
    #pragma unroll
    for (int i = 0; i < 8; i++) tot2 += red[i];
    float var = tot2 * (1.0f / 1023.0f);
    float rs = 1.0f / (sqrtf(var) + 1e-6f);

    float4 a4 = reinterpret_cast<const float4*>(ln_a)[tid];
    float4 b4 = reinterpret_cast<const float4*>(ln_b)[tid];
    float y0 = a4.x * (dx0 * rs) + b4.x;
    float y1 = a4.y * (dx1 * rs) + b4.y;
    float y2 = a4.z * (dx2 * rs) + b4.z;
    float y3 = a4.w * (dx3 * rs) + b4.w;

    __nv_bfloat162* orow = reinterpret_cast<__nv_bfloat162*>(g_xbf + (size_t)r * DIM);
    orow[tid*2]   = __floats2bfloat162_rn(y0, y1);
    orow[tid*2+1] = __floats2bfloat162_rn(y2, y3);
}

// ---------------- K2: transpose+convert Wq,Wk -> bf16 [in][out]; zero bias accums ----------------
__global__ void tconv_kernel(const float* __restrict__ Wq, const float* __restrict__ Wk) {
    __shared__ float t[32][33];
    if (blockIdx.x == 0 && blockIdx.y == 0 && blockIdx.z == 0) {
        for (int i = threadIdx.x; i < DIM; i += 256) { g_ub[i] = 0.f; g_vb[i] = 0.f; }
        if (threadIdx.x == 0) g_cdot = 0.f;
    }
    int i0 = blockIdx.x * 32;
    int o0 = blockIdx.y * 32;
    const float* src = blockIdx.z ? Wk : Wq;
    __nv_bfloat16* dst = blockIdx.z ? g_wkt : g_wqt;
    int c = threadIdx.x & 31, r = threadIdx.x >> 5;   // 8 rows/iter
    #pragma unroll
    for (int rr = 0; rr < 4; rr++) {
        int row = rr * 8 + r;
        t[row][c] = src[(size_t)(o0 + row) * DIM + i0 + c];
    }
    __syncthreads();
    #pragma unroll
    for (int rr = 0; rr < 4; rr++) {
        int row = rr * 8 + r;
        dst[(size_t)(i0 + row) * DIM + o0 + c] = __float2bfloat16(t[c][row]);
    }
}

// ---------------- K3: templated 3-stage bf16 GEMM (C[m,n] = sum_k A[m,k]*B[n,k]) --------
// MODE 0: Mt[j,i] = sum_o Wkt[j,o]*Wqt[i,o]   (grid 8x8,  out bf16 g_mt)
// MODE 1: y[s,j]  = sum_i Xbf[s,i]*Mt[j,i]    (grid 8x64, out bf16 g_ybf)
#define GBM 128
#define GBN 128
#define GBK 32
#define SPAD 40
#define GSTAGES 3
#define SMEMSZ (GSTAGES * (GBM + GBN) * SPAD * 2)

template <int MODE>
__global__ __launch_bounds__(256, 2) void gemm_tpl() {
    extern __shared__ __align__(16) char dynsm[];
    auto As = reinterpret_cast<__nv_bfloat16(*)[GBM][SPAD]>(dynsm);
    auto Bs = reinterpret_cast<__nv_bfloat16(*)[GBN][SPAD]>(dynsm + GSTAGES * GBM * SPAD * 2);

    const __nv_bfloat16* Ag = (MODE == 0) ? g_wkt : g_xbf;
    const __nv_bfloat16* Bg = (MODE == 0) ? g_wqt : g_mt;

    int tid  = threadIdx.x;
    int m0   = blockIdx.y * GBM;
    int n0   = blockIdx.x * GBN;
    int warp = tid >> 5, lane = tid & 31;
    int wm = warp >> 2, wn = warp & 3;      // 2 (M) x 4 (N) warps; warp tile 64x32
    int gid = lane >> 2, tig = lane & 3;

    float acc[4][4][4];
    #pragma unroll
    for (int a = 0; a < 4; a++)
        #pragma unroll
        for (int b = 0; b < 4; b++)
            #pragma unroll
            for (int c = 0; c < 4; c++) acc[a][b][c] = 0.f;

    auto load_stage = [&](int buf, int kt) {
        int k0 = kt * GBK;
        #pragma unroll
        for (int h = 0; h < 2; h++) {
            int chunk = tid + h * 256;       // 512 chunks of 16B per operand
            int row = chunk >> 2;
            int cc  = chunk & 3;
            cp_async16(&As[buf][row][cc*8], Ag + (size_t)(m0 + row) * DIM + k0 + cc*8);
            cp_async16(&Bs[buf][row][cc*8], Bg + (size_t)(n0 + row) * DIM + k0 + cc*8);
        }
        CP_COMMIT();
    };

    const int NT = DIM / GBK;   // 32
    load_stage(0, 0);
    load_stage(1, 1);

    for (int kt = 0; kt < NT; kt++) {
        if (kt < NT - 1) { CP_WAIT(1); } else { CP_WAIT(0); }
        __syncthreads();
        if (kt + 2 < NT) load_stage((kt + 2) % GSTAGES, kt + 2);
        int buf = kt % GSTAGES;

        #pragma unroll
        for (int ks = 0; ks < 2; ks++) {
            int col = ks * 16 + tig * 2;
            uint32_t af[4][4], bfr[4][2];
            #pragma unroll
            for (int mt = 0; mt < 4; mt++) {
                int arow = wm * 64 + mt * 16 + gid;
                af[mt][0] = *reinterpret_cast<const uint32_t*>(&As[buf][arow    ][col    ]);
                af[mt][1] = *reinterpret_cast<const uint32_t*>(&As[buf][arow + 8][col    ]);
                af[mt][2] = *reinterpret_cast<const uint32_t*>(&As[buf][arow    ][col + 8]);
                af[mt][3] = *reinterpret_cast<const uint32_t*>(&As[buf][arow + 8][col + 8]);
            }
            #pragma unroll
            for (int nt = 0; nt < 4; nt++) {
                int brow = wn * 32 + nt * 8 + gid;
                bfr[nt][0] = *reinterpret_cast<const uint32_t*>(&Bs[buf][brow][col    ]);
                bfr[nt][1] = *reinterpret_cast<const uint32_t*>(&Bs[buf][brow][col + 8]);
            }
            #pragma unroll
            for (int mt = 0; mt < 4; mt++)
                #pragma unroll
                for (int nt = 0; nt < 4; nt++)
                    mma16816(acc[mt][nt], af[mt], bfr[nt]);
        }
    }

    __nv_bfloat16* Cout = (MODE == 0) ? g_mt : g_ybf;
    #pragma unroll
    for (int mt = 0; mt < 4; mt++) {
        int row0 = m0 + wm * 64 + mt * 16 + gid;
        #pragma unroll
        for (int nt = 0; nt < 4; nt++) {
            int coln = n0 + wn * 32 + nt * 8 + tig * 2;
            *reinterpret_cast<__nv_bfloat162*>(&Cout[(size_t)row0 * DIM + coln]) =
                __floats2bfloat162_rn(acc[mt][nt][0], acc[mt][nt][1]);
            *reinterpret_cast<__nv_bfloat162*>(&Cout[(size_t)(row0 + 8) * DIM + coln]) =
                __floats2bfloat162_rn(acc[mt][nt][2], acc[mt][nt][3]);
        }
    }
}

// ---------------- K4: bias vectors via fp32 column reduction + atomics ----------------
// ub[i] = sum_o Wq[o,i]*bk[o] ; vb[i] = sum_o Wk[o,i]*bq[o] ; cdot = bq.bk
__global__ void bias2_kernel(const float* __restrict__ Wq, const float* __restrict__ Wk,
                             const float* __restrict__ bq, const float* __restrict__ bk) {
    int i  = blockIdx.x * 256 + threadIdx.x;
    int o0 = blockIdx.y * 32;
    const float* W  = blockIdx.z ? Wk : Wq;
    const float* bv = blockIdx.z ? bq : bk;
    float* dst      = blockIdx.z ? g_vb : g_ub;
    float s = 0.f;
    #pragma unroll 8
    for (int o = o0; o < o0 + 32; o++) s += W[(size_t)o * DIM + i] * bv[o];
    atomicAdd(&dst[i], s);
    if (blockIdx.z == 0 && blockIdx.x == 0 && threadIdx.x < 32) {
        int o = o0 + threadIdx.x;
        float c = bq[o] * bk[o];
        #pragma unroll
        for (int off = 16; off; off >>= 1) c += __shfl_xor_sync(0xffffffffu, c, off);
        if (threadIdx.x == 0) atomicAdd(&g_cdot, c);
    }
}

// ---------------- K5: band scores + 2-way softmax -> p_plus/p_minus/rowmask ----------------
__global__ void band_kernel(const int* __restrict__ eos) {
    int r = blockIdx.x * 8 + (threadIdx.x >> 5);   // one warp per row
    int lane = threadIdx.x & 31;
    int b = r >> 10, s = r & 1023;

    int ep = 0, em = 0;
    if (lane == 0) {
        if (s < SEQ - 1) ep = eos[((size_t)b * SEQ + s) * SEQ + (s + 1)];
        if (s > 0)       em = eos[((size_t)b * SEQ + s) * SEQ + (s - 1)];
    }
    ep = __shfl_sync(0xffffffffu, ep, 0);
    em = __shfl_sync(0xffffffffu, em, 0);
    bool vp = (ep != 0), vm = (em != 0);

    int rp = (r == NROWS - 1) ? r : r + 1;
    int rm = (r == 0) ? r : r - 1;

    const __nv_bfloat162* y2  = reinterpret_cast<const __nv_bfloat162*>(g_ybf + (size_t)r * DIM);
    const __nv_bfloat162* xp2 = reinterpret_cast<const __nv_bfloat162*>(g_xbf + (size_t)rp * DIM);
    const __nv_bfloat162* xm2 = reinterpret_cast<const __nv_bfloat162*>(g_xbf + (size_t)rm * DIM);
    const __nv_bfloat162* xs2 = reinterpret_cast<const __nv_bfloat162*>(g_xbf + (size_t)r * DIM);
    const float2*         ub2 = reinterpret_cast<const float2*>(g_ub);
    const float2*         vb2 = reinterpret_cast<const float2*>(g_vb);

    float dotp = 0.f, dotm = 0.f, as_ = 0.f, bp_ = 0.f, bm_ = 0.f;
    #pragma unroll
    for (int i = 0; i < 16; i++) {
        int d = lane + i * 32;
        float2 y  = __bfloat1622float2(y2[d]);
        float2 xp = __bfloat1622float2(xp2[d]);
        float2 xm = __bfloat1622float2(xm2[d]);
        float2 xs = __bfloat1622float2(xs2[d]);
        float2 ub = ub2[d];
        float2 vb = vb2[d];
        dotp += y.x * xp.x + y.y * xp.y;
        dotm += y.x * xm.x + y.y * xm.y;
        as_  += xs.x * ub.x + xs.y * ub.y;
        bp_  += xp.x * vb.x + xp.y * vb.y;
        bm_  += xm.x * vb.x + xm.y * vb.y;
    }
    #pragma unroll
    for (int o = 16; o; o >>= 1) {
        dotp += __shfl_xor_sync(0xffffffffu, dotp, o);
        dotm += __shfl_xor_sync(0xffffffffu, dotm, o);
        as_  += __shfl_xor_sync(0xffffffffu, as_,  o);
        bp_  += __shfl_xor_sync(0xffffffffu, bp_,  o);
        bm_  += __shfl_xor_sync(0xffffffffu, bm_,  o);
    }

    if (lane == 0) {
        float pp = 0.f, pm = 0.f;
        int mk = 0;
        if (!vp && !vm) {
            mk = 1;   // fully masked row -> uniform 1/1024 downstream
        } else {
            float cd = g_cdot;
            float sp = vp ? (dotp + as_ + bp_ + cd) * INV1024 : -INFINITY;
            float sm = vm ? (dotm + as_ + bm_ + cd) * INV1024 : -INFINITY;
            float mx = fmaxf(sp, sm);
            float e1 = vp ? expf(sp - mx) : 0.f;
            float e2 = vm ? expf(sm - mx) : 0.f;
            float z = e1 + e2;
            pp = e1 / z; pm = e2 / z;
        }
        g_pp[r] = pp; g_pm[r] = pm; g_msk[r] = mk;
    }
}

// ---------------- K6: per-batch fp64 exclusive prefix scan -> fp32 hi/lo split ----------------
__global__ void scan_kernel() {
    int b = blockIdx.x;
    int s = threadIdx.x;          // 1024 threads
    int r = b * SEQ + s;
    __shared__ double sd[SEQ];

    double logn = 0.0;
    if (s < SEQ - 1) {
        float Pp = g_msk[r]     ? INV1024 : g_pp[r];
        float Pm = g_msk[r + 1] ? INV1024 : g_pm[r + 1];
        float nb = sqrtf(Pp * Pm + 1e-9f);
        logn = (double)logf(nb + 1e-9f);
    }
    sd[s] = logn;
    __syncthreads();
    for (int off = 1; off < SEQ; off <<= 1) {
        double v = (s >= off) ? sd[s - off] : 0.0;
        __syncthreads();
        sd[s] += v;
        __syncthreads();
    }
    double c = (s == 0) ? 0.0 : sd[s - 1];
    float hi = (float)c;
    g_chi[r] = hi;
    g_clo[r] = (float)(c - (double)hi);
}

// ---------------- K7: assemble g and neibor, write both outputs (all fp32) ----------------
__global__ void out_kernel(float* __restrict__ out) {
    int b  = blockIdx.y;
    int s0 = blockIdx.x * 16;
    int tid = threadIdx.x;         // 256 threads, 4 t-values each

    __shared__ float chi_sh[SEQ];
    __shared__ float clo_sh[SEQ];
    __shared__ float pp_sh[SEQ];
    __shared__ float pm_sh[SEQ];
    __shared__ unsigned char mk_sh[SEQ];

    int base = b * SEQ;
    for (int i = tid; i < SEQ; i += 256) {
        chi_sh[i] = g_chi[base + i];
        clo_sh[i] = g_clo[base + i];
        pp_sh[i]  = g_pp[base + i];
        pm_sh[i]  = g_pm[base + i];
        mk_sh[i]  = (unsigned char)g_msk[base + i];
    }
    __syncthreads();

    float* gout = out;
    float* nout = out + (size_t)BATCH * SEQ * SEQ;
    int t0 = tid * 4;

    for (int i = 0; i < 16; i++) {
        int s = s0 + i;
        float chs = chi_sh[s], cls = clo_sh[s];
        float pps = pp_sh[s], pms = pm_sh[s];
        int ms = mk_sh[s];
        float4 gg, nn;
        float* gp = reinterpret_cast<float*>(&gg);
        float* np = reinterpret_cast<float*>(&nn);
        #pragma unroll
        for (int j = 0; j < 4; j++) {
            int t = t0 + j;
            int mt = mk_sh[t];
            float Pst = ms ? INV1024 : ((t == s + 1) ? pps : ((t == s - 1) ? pms : 0.f));
            float Pts = mt ? INV1024 : ((t == s - 1) ? pp_sh[t] : ((t == s + 1) ? pm_sh[t] : 0.f));
            float nb = sqrtf(Pst * Pts + 1e-9f);
            np[j] = nb;
            float gv;
            if (t == s) {
                gv = nb;                                   // diag: neibor[s,s]
            } else {
                // d = |c_t - c_s| with hi/lo compensated fp32 arithmetic
                float dh = (t > s) ? (chi_sh[t] - chs) : (chs - chi_sh[t]);
                float dl = (t > s) ? (clo_sh[t] - cls) : (cls - clo_sh[t]);
                gv = expf(dh + dl) + 1e-9f;                // off-diag: telescoped product
            }
            gp[j] = gv;
        }
        size_t o = ((size_t)(base + s)) * SEQ + t0;
        *reinterpret_cast<float4*>(gout + o) = gg;
        *reinterpret_cast<float4*>(nout + o) = nn;
    }
}

// ---------------- launch ----------------
extern "C" void kernel_launch(void* const* d_in, const int* in_sizes, int n_in,
                              void* d_out, int out_size) {
    const float* context = (const float*)d_in[0];
    const int*   eos     = (const int*)  d_in[1];
    const float* Wq      = (const float*)d_in[2];
    const float* bq      = (const float*)d_in[3];
    const float* Wk      = (const float*)d_in[4];
    const float* bk      = (const float*)d_in[5];
    const float* ln_a    = (const float*)d_in[6];
    const float* ln_b    = (const float*)d_in[7];
    float* out = (float*)d_out;

    cudaFuncSetAttribute(gemm_tpl<0>, cudaFuncAttributeMaxDynamicSharedMemorySize, SMEMSZ);
    cudaFuncSetAttribute(gemm_tpl<1>, cudaFuncAttributeMaxDynamicSharedMemorySize, SMEMSZ);

    ln_kernel<<<NROWS, 256>>>(context, ln_a, ln_b);
    tconv_kernel<<<dim3(32, 32, 2), 256>>>(Wq, Wk);
    gemm_tpl<0><<<dim3(DIM / GBN, DIM / GBM), 256, SMEMSZ>>>();      // Mt = Wk^T Wq
    bias2_kernel<<<dim3(4, 32, 2), 256>>>(Wq, Wk, bq, bk);
    gemm_tpl<1><<<dim3(DIM / GBN, NROWS / GBM), 256, SMEMSZ>>>();    // y = X * M (bf16)
    band_kernel<<<NROWS / 8, 256>>>(eos);
    scan_kernel<<<BATCH, SEQ>>>();
    out_kernel<<<dim3(SEQ / 16, BATCH), 256>>>(out);
}

// round 9
// speedup vs baseline: 1.4848x; 1.1046x over previous
#include <cuda_runtime.h>
#include <cuda_bf16.h>
#include <math.h>
#include <stdint.h>

// Problem constants (B=8, S=1024, D=1024)
#define BATCH 8
#define SEQ   1024
#define DIM   1024
#define NROWS (BATCH*SEQ)     // 8192
#define INV1024 (1.0f/1024.0f)

// ---------------- scratch (__device__ globals: no allocations allowed) ----------------
__device__ __nv_bfloat16 g_xbf[(size_t)NROWS*DIM];     // layernormed X, bf16   (16 MB)
__device__ __nv_bfloat16 g_wqt[(size_t)DIM*DIM];       // Wq transposed [i][o]  (2 MB)
__device__ __nv_bfloat16 g_wkt[(size_t)DIM*DIM];       // Wk transposed [j][o]  (2 MB)
__device__ __nv_bfloat16 g_mt [(size_t)DIM*DIM];       // Mt[j][i] = (Wq^T Wk)[i][j] (2 MB)
__device__ __nv_bfloat16 g_ybf[(size_t)NROWS*DIM];     // y = X * M, bf16       (16 MB)
__device__ float         g_ub[DIM];                    // Wq^T bk
__device__ float         g_vb[DIM];                    // Wk^T bq
__device__ float         g_cdot;                       // bq . bk
__device__ float         g_pp[NROWS];                  // p[s,s+1]
__device__ float         g_pm[NROWS];                  // p[s,s-1]
__device__ int           g_msk[NROWS];                 // row fully masked
__device__ float         g_chi[NROWS];                 // prefix sum hi (fp32)
__device__ float         g_clo[NROWS];                 // prefix sum lo (fp32)

// ---------------- helpers ----------------
__device__ __forceinline__ void cp_async16(void* sm, const void* gm) {
    unsigned sa = (unsigned)__cvta_generic_to_shared(sm);
    asm volatile("cp.async.cg.shared.global [%0], [%1], 16;\n" :: "r"(sa), "l"(gm) : "memory");
}
#define CP_COMMIT() asm volatile("cp.async.commit_group;\n" ::)
#define CP_WAIT(n)  asm volatile("cp.async.wait_group %0;\n" :: "n"(n))

__device__ __forceinline__ void mma16816(float* c, const uint32_t* a, const uint32_t* b) {
    asm volatile(
        "mma.sync.aligned.m16n8k16.row.col.f32.bf16.bf16.f32 "
        "{%0,%1,%2,%3}, {%4,%5,%6,%7}, {%8,%9}, {%0,%1,%2,%3};\n"
        : "+f"(c[0]), "+f"(c[1]), "+f"(c[2]), "+f"(c[3])
        : "r"(a[0]), "r"(a[1]), "r"(a[2]), "r"(a[3]), "r"(b[0]), "r"(b[1]));
}

__device__ __forceinline__ void ldsm_x4(uint32_t* r, uint32_t saddr) {
    asm volatile("ldmatrix.sync.aligned.m8n8.x4.shared.b16 {%0,%1,%2,%3}, [%4];"
        : "=r"(r[0]), "=r"(r[1]), "=r"(r[2]), "=r"(r[3]) : "r"(saddr));
}

__device__ __forceinline__ uint32_t smem_u32(const void* p) {
    return (uint32_t)__cvta_generic_to_shared(p);
}

// ---------------- K1: LayerNorm (ddof=1, eps added to std) -> bf16; zero bias accums ----------------
__global__ void ln_kernel(const float* __restrict__ ctx,
                          const float* __restrict__ ln_a,
                          const float* __restrict__ ln_b) {
    int r = blockIdx.x;            // 0..8191
    int tid = threadIdx.x;         // 256 threads, 4 elems each
    if (r == 0) {                  // zero bias accumulators (tconv runs after, atomics safe)
        for (int i = tid; i < DIM; i += 256) { g_ub[i] = 0.f; g_vb[i] = 0.f; }
        if (tid == 0) g_cdot = 0.f;
    }
    const float4* xrow = reinterpret_cast<const float4*>(ctx + (size_t)r * DIM);
    float4 v = xrow[tid];

    __shared__ float red[8];
    float s = v.x + v.y + v.z + v.w;
    #pragma unroll
    for (int o = 16; o; o >>= 1) s += __shfl_xor_sync(0xffffffffu, s, o);
    if ((tid & 31) == 0) red[tid >> 5] = s;
    __syncthreads();
    float tot = 0.f;
    #pragma unroll
    for (int i = 0; i < 8; i++) tot += red[i];
    float mean = tot * (1.0f / 1024.0f);
    __syncthreads();
    float dx0 = v.x - mean, dx1 = v.y - mean, dx2 = v.z - mean, dx3 = v.w - mean;
    float s2 = dx0*dx0 + dx1*dx1 + dx2*dx2 + dx3*dx3;
    #pragma unroll
    for (int o = 16; o; o >>= 1) s2 += __shfl_xor_sync(0xffffffffu, s2, o);
    if ((tid & 31) == 0) red[tid >> 5] = s2;
    __syncthreads();
    float tot2 = 0.f;
    #pragma unroll
    for (int i = 0; i < 8; i++) tot2 += red[i];
    float var = tot2 * (1.0f / 1023.0f);
    float rs = 1.0f / (sqrtf(var) + 1e-6f);

    float4 a4 = reinterpret_cast<const float4*>(ln_a)[tid];
    float4 b4 = reinterpret_cast<const float4*>(ln_b)[tid];
    float y0 = a4.x * (dx0 * rs) + b4.x;
    float y1 = a4.y * (dx1 * rs) + b4.y;
    float y2 = a4.z * (dx2 * rs) + b4.z;
    float y3 = a4.w * (dx3 * rs) + b4.w;

    __nv_bfloat162* orow = reinterpret_cast<__nv_bfloat162*>(g_xbf + (size_t)r * DIM);
    orow[tid*2]   = __floats2bfloat162_rn(y0, y1);
    orow[tid*2+1] = __floats2bfloat162_rn(y2, y3);
}

// ---------------- K2: transpose+convert Wq,Wk -> bf16 [in][out] + fused bias matvecs --------
// z=0: g_wqt, ub[i] += sum_o Wq[o,i]*bk[o] ;  z=1: g_wkt, vb[i] += sum_o Wk[o,i]*bq[o]
__global__ void tconv_kernel(const float* __restrict__ Wq, const float* __restrict__ Wk,
                             const float* __restrict__ bq, const float* __restrict__ bk) {
    __shared__ float t[32][33];
    __shared__ float red2[8][33];
    int i0 = blockIdx.x * 32;
    int o0 = blockIdx.y * 32;
    int bz = blockIdx.z;
    const float* src = bz ? Wk : Wq;
    const float* bv  = bz ? bq : bk;
    float* dstb      = bz ? g_vb : g_ub;
    __nv_bfloat16* dst = bz ? g_wkt : g_wqt;
    int tid = threadIdx.x;
    int c = tid & 31, r = tid >> 5;   // 8 rows/iter
    #pragma unroll
    for (int rr = 0; rr < 4; rr++) {
        int row = rr * 8 + r;
        t[row][c] = src[(size_t)(o0 + row) * DIM + i0 + c];
    }
    __syncthreads();
    #pragma unroll
    for (int rr = 0; rr < 4; rr++) {
        int row = rr * 8 + r;
        dst[(size_t)(i0 + row) * DIM + o0 + c] = __float2bfloat16(t[c][row]);
    }
    // fused bias partial: sum over this o-chunk for column i0+c
    float p = 0.f;
    #pragma unroll
    for (int k = 0; k < 4; k++) {
        int row = r + k * 8;
        p += t[row][c] * bv[o0 + row];
    }
    red2[r][c] = p;
    __syncthreads();
    if (r == 0) {
        float sum = 0.f;
        #pragma unroll
        for (int k = 0; k < 8; k++) sum += red2[k][c];
        atomicAdd(&dstb[i0 + c], sum);
    }
    if (bz == 0 && blockIdx.x == 0 && tid < 32) {
        float cd = bq[o0 + tid] * bk[o0 + tid];
        #pragma unroll
        for (int off = 16; off; off >>= 1) cd += __shfl_xor_sync(0xffffffffu, cd, off);
        if (tid == 0) atomicAdd(&g_cdot, cd);
    }
}

// ---------------- K3: templated 3-stage bf16 GEMM with ldmatrix fragments --------
// MODE 0: Mt[j,i] = sum_o Wkt[j,o]*Wqt[i,o]   (grid 8x8,  out bf16 g_mt)
// MODE 1: y[s,j]  = sum_i Xbf[s,i]*Mt[j,i]    (grid 8x64, out bf16 g_ybf)
#define GBM 128
#define GBN 128
#define GBK 32
#define SPAD 40
#define GSTAGES 3
#define SMEMSZ (GSTAGES * (GBM + GBN) * SPAD * 2)

template <int MODE>
__global__ __launch_bounds__(256, 2) void gemm_tpl() {
    extern __shared__ __align__(16) char dynsm[];
    auto As = reinterpret_cast<__nv_bfloat16(*)[GBM][SPAD]>(dynsm);
    auto Bs = reinterpret_cast<__nv_bfloat16(*)[GBN][SPAD]>(dynsm + GSTAGES * GBM * SPAD * 2);

    const __nv_bfloat16* Ag = (MODE == 0) ? g_wkt : g_xbf;
    const __nv_bfloat16* Bg = (MODE == 0) ? g_wqt : g_mt;

    int tid  = threadIdx.x;
    int m0   = blockIdx.y * GBM;
    int n0   = blockIdx.x * GBN;
    int warp = tid >> 5, lane = tid & 31;
    int wm = warp >> 2, wn = warp & 3;      // 2 (M) x 4 (N) warps; warp tile 64x32
    int gid = lane >> 2, tig = lane & 3;
    int quad = lane >> 3, rowin = lane & 7; // ldmatrix address lanes

    float acc[4][4][4];
    #pragma unroll
    for (int a = 0; a < 4; a++)
        #pragma unroll
        for (int b = 0; b < 4; b++)
            #pragma unroll
            for (int c = 0; c < 4; c++) acc[a][b][c] = 0.f;

    auto load_stage = [&](int buf, int kt) {
        int k0 = kt * GBK;
        #pragma unroll
        for (int h = 0; h < 2; h++) {
            int chunk = tid + h * 256;       // 512 chunks of 16B per operand
            int row = chunk >> 2;
            int cc  = chunk & 3;
            cp_async16(&As[buf][row][cc*8], Ag + (size_t)(m0 + row) * DIM + k0 + cc*8);
            cp_async16(&Bs[buf][row][cc*8], Bg + (size_t)(n0 + row) * DIM + k0 + cc*8);
        }
        CP_COMMIT();
    };

    const int NT = DIM / GBK;   // 32
    load_stage(0, 0);
    load_stage(1, 1);

    // per-thread ldmatrix address components (element offsets within a stage)
    // A: row = wm*64 + mt*16 + rowin + (quad&1)*8 ; col = ks*16 + (quad>>1)*8
    // B: row = wn*32 + ntp*16 + rowin + (quad>>1)*8 ; col = ks*16 + (quad&1)*8
    int a_row0 = wm * 64 + rowin + (quad & 1) * 8;
    int a_col0 = (quad >> 1) * 8;
    int b_row0 = wn * 32 + rowin + (quad >> 1) * 8;
    int b_col0 = (quad & 1) * 8;

    for (int kt = 0; kt < NT; kt++) {
        if (kt < NT - 1) { CP_WAIT(1); } else { CP_WAIT(0); }
        __syncthreads();
        if (kt + 2 < NT) load_stage((kt + 2) % GSTAGES, kt + 2);
        int buf = kt % GSTAGES;
        uint32_t abase = smem_u32(&As[buf][0][0]);
        uint32_t bbase = smem_u32(&Bs[buf][0][0]);

        #pragma unroll
        for (int ks = 0; ks < 2; ks++) {
            uint32_t af[4][4], bfr[4][2];
            #pragma unroll
            for (int mt = 0; mt < 4; mt++)
                ldsm_x4(af[mt], abase + ((a_row0 + mt * 16) * SPAD + ks * 16 + a_col0) * 2);
            #pragma unroll
            for (int ntp = 0; ntp < 2; ntp++)
                ldsm_x4(&bfr[ntp * 2][0], bbase + ((b_row0 + ntp * 16) * SPAD + ks * 16 + b_col0) * 2);
            #pragma unroll
            for (int mt = 0; mt < 4; mt++)
                #pragma unroll
                for (int nt = 0; nt < 4; nt++)
                    mma16816(acc[mt][nt], af[mt], bfr[nt]);
        }
    }

    __nv_bfloat16* Cout = (MODE == 0) ? g_mt : g_ybf;
    #pragma unroll
    for (int mt = 0; mt < 4; mt++) {
        int row0 = m0 + wm * 64 + mt * 16 + gid;
        #pragma unroll
        for (int nt = 0; nt < 4; nt++) {
            int coln = n0 + wn * 32 + nt * 8 + tig * 2;
            *reinterpret_cast<__nv_bfloat162*>(&Cout[(size_t)row0 * DIM + coln]) =
                __floats2bfloat162_rn(acc[mt][nt][0], acc[mt][nt][1]);
            *reinterpret_cast<__nv_bfloat162*>(&Cout[(size_t)(row0 + 8) * DIM + coln]) =
                __floats2bfloat162_rn(acc[mt][nt][2], acc[mt][nt][3]);
        }
    }
}

// ---------------- K4: band scores + 2-way softmax -> p_plus/p_minus/rowmask ----------------
__global__ void band_kernel(const int* __restrict__ eos) {
    int r = blockIdx.x * 8 + (threadIdx.x >> 5);   // one warp per row
    int lane = threadIdx.x & 31;
    int b = r >> 10, s = r & 1023;

    int ep = 0, em = 0;
    if (lane == 0) {
        if (s < SEQ - 1) ep = eos[((size_t)b * SEQ + s) * SEQ + (s + 1)];
        if (s > 0)       em = eos[((size_t)b * SEQ + s) * SEQ + (s - 1)];
    }
    ep = __shfl_sync(0xffffffffu, ep, 0);
    em = __shfl_sync(0xffffffffu, em, 0);
    bool vp = (ep != 0), vm = (em != 0);

    int rp = (r == NROWS - 1) ? r : r + 1;
    int rm = (r == 0) ? r : r - 1;

    const __nv_bfloat162* y2  = reinterpret_cast<const __nv_bfloat162*>(g_ybf + (size_t)r * DIM);
    const __nv_bfloat162* xp2 = reinterpret_cast<const __nv_bfloat162*>(g_xbf + (size_t)rp * DIM);
    const __nv_bfloat162* xm2 = reinterpret_cast<const __nv_bfloat162*>(g_xbf + (size_t)rm * DIM);
    const __nv_bfloat162* xs2 = reinterpret_cast<const __nv_bfloat162*>(g_xbf + (size_t)r * DIM);
    const float2*         ub2 = reinterpret_cast<const float2*>(g_ub);
    const float2*         vb2 = reinterpret_cast<const float2*>(g_vb);

    float dotp = 0.f, dotm = 0.f, as_ = 0.f, bp_ = 0.f, bm_ = 0.f;
    #pragma unroll
    for (int i = 0; i < 16; i++) {
        int d = lane + i * 32;
        float2 y  = __bfloat1622float2(y2[d]);
        float2 xp = __bfloat1622float2(xp2[d]);
        float2 xm = __bfloat1622float2(xm2[d]);
        float2 xs = __bfloat1622float2(xs2[d]);
        float2 ub = ub2[d];
        float2 vb = vb2[d];
        dotp += y.x * xp.x + y.y * xp.y;
        dotm += y.x * xm.x + y.y * xm.y;
        as_  += xs.x * ub.x + xs.y * ub.y;
        bp_  += xp.x * vb.x + xp.y * vb.y;
        bm_  += xm.x * vb.x + xm.y * vb.y;
    }
    #pragma unroll
    for (int o = 16; o; o >>= 1) {
        dotp += __shfl_xor_sync(0xffffffffu, dotp, o);
        dotm += __shfl_xor_sync(0xffffffffu, dotm, o);
        as_  += __shfl_xor_sync(0xffffffffu, as_,  o);
        bp_  += __shfl_xor_sync(0xffffffffu, bp_,  o);
        bm_  += __shfl_xor_sync(0xffffffffu, bm_,  o);
    }

    if (lane == 0) {
        float pp = 0.f, pm = 0.f;
        int mk = 0;
        if (!vp && !vm) {
            mk = 1;   // fully masked row -> uniform 1/1024 downstream
        } else {
            float cd = g_cdot;
            float sp = vp ? (dotp + as_ + bp_ + cd) * INV1024 : -INFINITY;
            float sm = vm ? (dotm + as_ + bm_ + cd) * INV1024 : -INFINITY;
            float mx = fmaxf(sp, sm);
            float e1 = vp ? expf(sp - mx) : 0.f;
            float e2 = vm ? expf(sm - mx) : 0.f;
            float z = e1 + e2;
            pp = e1 / z; pm = e2 / z;
        }
        g_pp[r] = pp; g_pm[r] = pm; g_msk[r] = mk;
    }
}

// ---------------- K5: per-batch fp64 exclusive prefix scan -> fp32 hi/lo split ----------------
__global__ void scan_kernel() {
    int b = blockIdx.x;
    int s = threadIdx.x;          // 1024 threads
    int r = b * SEQ + s;
    __shared__ double sd[SEQ];

    double logn = 0.0;
    if (s < SEQ - 1) {
        float Pp = g_msk[r]     ? INV1024 : g_pp[r];
        float Pm = g_msk[r + 1] ? INV1024 : g_pm[r + 1];
        float nb = sqrtf(Pp * Pm + 1e-9f);
        logn = (double)logf(nb + 1e-9f);
    }
    sd[s] = logn;
    __syncthreads();
    for (int off = 1; off < SEQ; off <<= 1) {
        double v = (s >= off) ? sd[s - off] : 0.0;
        __syncthreads();
        sd[s] += v;
        __syncthreads();
    }
    double c = (s == 0) ? 0.0 : sd[s - 1];
    float hi = (float)c;
    g_chi[r] = hi;
    g_clo[r] = (float)(c - (double)hi);
}

// ---------------- K6: assemble g and neibor, write both outputs (all fp32) ----------------
__global__ void out_kernel(float* __restrict__ out) {
    int b  = blockIdx.y;
    int s0 = blockIdx.x * 16;
    int tid = threadIdx.x;         // 256 threads, 4 t-values each

    __shared__ float chi_sh[SEQ];
    __shared__ float clo_sh[SEQ];
    __shared__ float pp_sh[SEQ];
    __shared__ float pm_sh[SEQ];
    __shared__ unsigned char mk_sh[SEQ];

    int base = b * SEQ;
    for (int i = tid; i < SEQ; i += 256) {
        chi_sh[i] = g_chi[base + i];
        clo_sh[i] = g_clo[base + i];
        pp_sh[i]  = g_pp[base + i];
        pm_sh[i]  = g_pm[base + i];
        mk_sh[i]  = (unsigned char)g_msk[base + i];
    }
    __syncthreads();

    float* gout = out;
    float* nout = out + (size_t)BATCH * SEQ * SEQ;
    int t0 = tid * 4;

    for (int i = 0; i < 16; i++) {
        int s = s0 + i;
        float chs = chi_sh[s], cls = clo_sh[s];
        float pps = pp_sh[s], pms = pm_sh[s];
        int ms = mk_sh[s];
        float4 gg, nn;
        float* gp = reinterpret_cast<float*>(&gg);
        float* np = reinterpret_cast<float*>(&nn);
        #pragma unroll
        for (int j = 0; j < 4; j++) {
            int t = t0 + j;
            int mt = mk_sh[t];
            float Pst = ms ? INV1024 : ((t == s + 1) ? pps : ((t == s - 1) ? pms : 0.f));
            float Pts = mt ? INV1024 : ((t == s - 1) ? pp_sh[t] : ((t == s + 1) ? pm_sh[t] : 0.f));
            float nb = sqrtf(Pst * Pts + 1e-9f);
            np[j] = nb;
            float gv;
            if (t == s) {
                gv = nb;                                   // diag: neibor[s,s]
            } else {
                // d = |c_t - c_s| with hi/lo compensated fp32 arithmetic
                float dh = (t > s) ? (chi_sh[t] - chs) : (chs - chi_sh[t]);
                float dl = (t > s) ? (clo_sh[t] - cls) : (cls - clo_sh[t]);
                gv = expf(dh + dl) + 1e-9f;                // off-diag: telescoped product
            }
            gp[j] = gv;
        }
        size_t o = ((size_t)(base + s)) * SEQ + t0;
        *reinterpret_cast<float4*>(gout + o) = gg;
        *reinterpret_cast<float4*>(nout + o) = nn;
    }
}

// ---------------- launch ----------------
extern "C" void kernel_launch(void* const* d_in, const int* in_sizes, int n_in,
                              void* d_out, int out_size) {
    const float* context = (const float*)d_in[0];
    const int*   eos     = (const int*)  d_in[1];
    const float* Wq      = (const float*)d_in[2];
    const float* bq      = (const float*)d_in[3];
    const float* Wk      = (const float*)d_in[4];
    const float* bk      = (const float*)d_in[5];
    const float* ln_a    = (const float*)d_in[6];
    const float* ln_b    = (const float*)d_in[7];
    float* out = (float*)d_out;

    cudaFuncSetAttribute(gemm_tpl<0>, cudaFuncAttributeMaxDynamicSharedMemorySize, SMEMSZ);
    cudaFuncSetAttribute(gemm_tpl<1>, cudaFuncAttributeMaxDynamicSharedMemorySize, SMEMSZ);

    ln_kernel<<<NROWS, 256>>>(context, ln_a, ln_b);
    tconv_kernel<<<dim3(32, 32, 2), 256>>>(Wq, Wk, bq, bk);
    gemm_tpl<0><<<dim3(DIM / GBN, DIM / GBM), 256, SMEMSZ>>>();      // Mt = Wk^T Wq
    gemm_tpl<1><<<dim3(DIM / GBN, NROWS / GBM), 256, SMEMSZ>>>();    // y = X * M (bf16)
    band_kernel<<<NROWS / 8, 256>>>(eos);
    scan_kernel<<<BATCH, SEQ>>>();
    out_kernel<<<dim3(SEQ / 16, BATCH), 256>>>(out);
}

// round 11
// speedup vs baseline: 1.5967x; 1.0754x over previous
#include <cuda_runtime.h>
#include <cuda_bf16.h>
#include <math.h>
#include <stdint.h>

// Problem constants (B=8, S=1024, D=1024)
#define BATCH 8
#define SEQ   1024
#define DIM   1024
#define NROWS (BATCH*SEQ)     // 8192
#define INV1024 (1.0f/1024.0f)

// ---------------- scratch (__device__ globals: no allocations allowed) ----------------
__device__ __nv_bfloat16 g_xbf[(size_t)NROWS*DIM];     // layernormed X, bf16   (16 MB)
__device__ __nv_bfloat16 g_wqt[(size_t)DIM*DIM];       // Wq transposed [i][o]  (2 MB)
__device__ __nv_bfloat16 g_wkt[(size_t)DIM*DIM];       // Wk transposed [j][o]  (2 MB)
__device__ __nv_bfloat16 g_mt [(size_t)DIM*DIM];       // Mt[j][i] = (Wq^T Wk)[i][j] (2 MB)
__device__ float         g_ub[DIM];                    // Wq^T bk
__device__ float         g_vb[DIM];                    // Wk^T bq
__device__ float         g_cdot;                       // bq . bk
__device__ float         g_dotp[NROWS];                // y[r] . x[r+1]  (atomic accum)
__device__ float         g_dotm[NROWS];                // y[r] . x[r-1]
__device__ float         g_as [NROWS];                 // x[r] . ub
__device__ float         g_bv [NROWS];                 // x[r] . vb
__device__ float         g_pp[NROWS];                  // p[s,s+1]
__device__ float         g_pm[NROWS];                  // p[s,s-1]
__device__ int           g_msk[NROWS];                 // row fully masked
__device__ float         g_chi[NROWS];                 // prefix sum hi (fp32)
__device__ float         g_clo[NROWS];                 // prefix sum lo (fp32)

// ---------------- helpers ----------------
__device__ __forceinline__ void cp_async16(void* sm, const void* gm) {
    unsigned sa = (unsigned)__cvta_generic_to_shared(sm);
    asm volatile("cp.async.cg.shared.global [%0], [%1], 16;\n" :: "r"(sa), "l"(gm) : "memory");
}
#define CP_COMMIT() asm volatile("cp.async.commit_group;\n" ::)
#define CP_WAIT(n)  asm volatile("cp.async.wait_group %0;\n" :: "n"(n))

__device__ __forceinline__ void mma16816(float* c, const uint32_t* a, const uint32_t* b) {
    asm volatile(
        "mma.sync.aligned.m16n8k16.row.col.f32.bf16.bf16.f32 "
        "{%0,%1,%2,%3}, {%4,%5,%6,%7}, {%8,%9}, {%0,%1,%2,%3};\n"
        : "+f"(c[0]), "+f"(c[1]), "+f"(c[2]), "+f"(c[3])
        : "r"(a[0]), "r"(a[1]), "r"(a[2]), "r"(a[3]), "r"(b[0]), "r"(b[1]));
}

__device__ __forceinline__ void ldsm_x4(uint32_t* r, uint32_t saddr) {
    asm volatile("ldmatrix.sync.aligned.m8n8.x4.shared.b16 {%0,%1,%2,%3}, [%4];"
        : "=r"(r[0]), "=r"(r[1]), "=r"(r[2]), "=r"(r[3]) : "r"(saddr));
}

__device__ __forceinline__ uint32_t smem_u32(const void* p) {
    return (uint32_t)__cvta_generic_to_shared(p);
}

// ---------------- K1: LayerNorm (ddof=1, eps on std) -> bf16; zero accumulators ----------------
__global__ void ln_kernel(const float* __restrict__ ctx,
                          const float* __restrict__ ln_a,
                          const float* __restrict__ ln_b) {
    int r = blockIdx.x;            // 0..8191
    int tid = threadIdx.x;         // 256 threads, 4 elems each
    if (r == 0) {                  // zero all atomic accumulators (runs before tconv/gemm1)
        for (int i = tid; i < DIM; i += 256) { g_ub[i] = 0.f; g_vb[i] = 0.f; }
        for (int i = tid; i < NROWS; i += 256) {
            g_dotp[i] = 0.f; g_dotm[i] = 0.f; g_as[i] = 0.f; g_bv[i] = 0.f;
        }
        if (tid == 0) g_cdot = 0.f;
    }
    const float4* xrow = reinterpret_cast<const float4*>(ctx + (size_t)r * DIM);
    float4 v = xrow[tid];

    __shared__ float red[8];
    float s = v.x + v.y + v.z + v.w;
    #pragma unroll
    for (int o = 16; o; o >>= 1) s += __shfl_xor_sync(0xffffffffu, s, o);
    if ((tid & 31) == 0) red[tid >> 5] = s;
    __syncthreads();
    float tot = 0.f;
    #pragma unroll
    for (int i = 0; i < 8; i++) tot += red[i];
    float mean = tot * (1.0f / 1024.0f);
    __syncthreads();
    float dx0 = v.x - mean, dx1 = v.y - mean, dx2 = v.z - mean, dx3 = v.w - mean;
    float s2 = dx0*dx0 + dx1*dx1 + dx2*dx2 + dx3*dx3;
    #pragma unroll
    for (int o = 16; o; o >>= 1) s2 += __shfl_xor_sync(0xffffffffu, s2, o);
    if ((tid & 31) == 0) red[tid >> 5] = s2;
    __syncthreads();
    float tot2 = 0.f;
    #pragma unroll
    for (int i = 0; i < 8; i++) tot2 += red[i];
    float var = tot2 * (1.0f / 1023.0f);
    float rs = 1.0f / (sqrtf(var) + 1e-6f);

    float4 a4 = reinterpret_cast<const float4*>(ln_a)[tid];
    float4 b4 = reinterpret_cast<const float4*>(ln_b)[tid];
    float y0 = a4.x * (dx0 * rs) + b4.x;
    float y1 = a4.y * (dx1 * rs) + b4.y;
    float y2 = a4.z * (dx2 * rs) + b4.z;
    float y3 = a4.w * (dx3 * rs) + b4.w;

    __nv_bfloat162* orow = reinterpret_cast<__nv_bfloat162*>(g_xbf + (size_t)r * DIM);
    orow[tid*2]   = __floats2bfloat162_rn(y0, y1);
    orow[tid*2+1] = __floats2bfloat162_rn(y2, y3);
}

// ---------------- K2: transpose+convert Wq,Wk -> bf16 [in][out] + fused bias matvecs --------
__global__ void tconv_kernel(const float* __restrict__ Wq, const float* __restrict__ Wk,
                             const float* __restrict__ bq, const float* __restrict__ bk) {
    __shared__ float t[32][33];
    __shared__ float red2[8][33];
    int i0 = blockIdx.x * 32;
    int o0 = blockIdx.y * 32;
    int bz = blockIdx.z;
    const float* src = bz ? Wk : Wq;
    const float* bv  = bz ? bq : bk;
    float* dstb      = bz ? g_vb : g_ub;
    __nv_bfloat16* dst = bz ? g_wkt : g_wqt;
    int tid = threadIdx.x;
    int c = tid & 31, r = tid >> 5;   // 8 rows/iter
    #pragma unroll
    for (int rr = 0; rr < 4; rr++) {
        int row = rr * 8 + r;
        t[row][c] = src[(size_t)(o0 + row) * DIM + i0 + c];
    }
    __syncthreads();
    #pragma unroll
    for (int rr = 0; rr < 4; rr++) {
        int row = rr * 8 + r;
        dst[(size_t)(i0 + row) * DIM + o0 + c] = __float2bfloat16(t[c][row]);
    }
    float p = 0.f;
    #pragma unroll
    for (int k = 0; k < 4; k++) {
        int row = r + k * 8;
        p += t[row][c] * bv[o0 + row];
    }
    red2[r][c] = p;
    __syncthreads();
    if (r == 0) {
        float sum = 0.f;
        #pragma unroll
        for (int k = 0; k < 8; k++) sum += red2[k][c];
        atomicAdd(&dstb[i0 + c], sum);
    }
    if (bz == 0 && blockIdx.x == 0 && tid < 32) {
        float cd = bq[o0 + tid] * bk[o0 + tid];
        #pragma unroll
        for (int off = 16; off; off >>= 1) cd += __shfl_xor_sync(0xffffffffu, cd, off);
        if (tid == 0) atomicAdd(&g_cdot, cd);
    }
}

// ---------------- K3: templated 3-stage bf16 GEMM, GBK=64, ldmatrix fragments --------
// MODE 0: Mt[j,i] = sum_o Wkt[j,o]*Wqt[i,o]   (grid 8x8, writes bf16 g_mt)
// MODE 1: y[s,j]  = sum_i Xbf[s,i]*Mt[j,i]    (grid 8x64) -> FUSED band-dot epilogue,
//         no y store: atomicAdd partial dotp/dotm/as/bv per row.
#define GBM 128
#define GBN 128
#define GBK 64
#define SPAD 72
#define GSTAGES 3
#define SMEMSZ (GSTAGES * (GBM + GBN) * SPAD * 2)   // 110592 B

template <int MODE>
__global__ __launch_bounds__(256, 2) void gemm_tpl() {
    extern __shared__ __align__(16) char dynsm[];
    auto As = reinterpret_cast<__nv_bfloat16(*)[GBM][SPAD]>(dynsm);
    auto Bs = reinterpret_cast<__nv_bfloat16(*)[GBN][SPAD]>(dynsm + GSTAGES * GBM * SPAD * 2);

    const __nv_bfloat16* Ag = (MODE == 0) ? g_wkt : g_xbf;
    const __nv_bfloat16* Bg = (MODE == 0) ? g_wqt : g_mt;

    int tid  = threadIdx.x;
    int m0   = blockIdx.y * GBM;
    int n0   = blockIdx.x * GBN;
    int warp = tid >> 5, lane = tid & 31;
    int wm = warp >> 2, wn = warp & 3;      // 2 (M) x 4 (N) warps; warp tile 64x32
    int gid = lane >> 2, tig = lane & 3;
    int quad = lane >> 3, rowin = lane & 7; // ldmatrix address lanes

    float acc[4][4][4];
    #pragma unroll
    for (int a = 0; a < 4; a++)
        #pragma unroll
        for (int b = 0; b < 4; b++)
            #pragma unroll
            for (int c = 0; c < 4; c++) acc[a][b][c] = 0.f;

    auto load_stage = [&](int buf, int kt) {
        int k0 = kt * GBK;
        #pragma unroll
        for (int h = 0; h < 4; h++) {
            int chunk = tid + h * 256;       // 1024 chunks of 16B per operand
            int row = chunk >> 3;
            int cc  = chunk & 7;
            cp_async16(&As[buf][row][cc*8], Ag + (size_t)(m0 + row) * DIM + k0 + cc*8);
            cp_async16(&Bs[buf][row][cc*8], Bg + (size_t)(n0 + row) * DIM + k0 + cc*8);
        }
        CP_COMMIT();
    };

    const int NT = DIM / GBK;   // 16
    load_stage(0, 0);
    load_stage(1, 1);

    int a_row0 = wm * 64 + rowin + (quad & 1) * 8;
    int a_col0 = (quad >> 1) * 8;
    int b_row0 = wn * 32 + rowin + (quad >> 1) * 8;
    int b_col0 = (quad & 1) * 8;

    for (int kt = 0; kt < NT; kt++) {
        if (kt < NT - 1) { CP_WAIT(1); } else { CP_WAIT(0); }
        __syncthreads();
        if (kt + 2 < NT) load_stage((kt + 2) % GSTAGES, kt + 2);
        int buf = kt % GSTAGES;
        uint32_t abase = smem_u32(&As[buf][0][0]);
        uint32_t bbase = smem_u32(&Bs[buf][0][0]);

        #pragma unroll
        for (int ks = 0; ks < 4; ks++) {
            uint32_t af[4][4], bfr[4][2];
            #pragma unroll
            for (int mt = 0; mt < 4; mt++)
                ldsm_x4(af[mt], abase + ((a_row0 + mt * 16) * SPAD + ks * 16 + a_col0) * 2);
            #pragma unroll
            for (int ntp = 0; ntp < 2; ntp++)
                ldsm_x4(&bfr[ntp * 2][0], bbase + ((b_row0 + ntp * 16) * SPAD + ks * 16 + b_col0) * 2);
            #pragma unroll
            for (int mt = 0; mt < 4; mt++)
                #pragma unroll
                for (int nt = 0; nt < 4; nt++)
                    mma16816(acc[mt][nt], af[mt], bfr[nt]);
        }
    }

    if (MODE == 0) {
        #pragma unroll
        for (int mt = 0; mt < 4; mt++) {
            int row0 = m0 + wm * 64 + mt * 16 + gid;
            #pragma unroll
            for (int nt = 0; nt < 4; nt++) {
                int coln = n0 + wn * 32 + nt * 8 + tig * 2;
                *reinterpret_cast<__nv_bfloat162*>(&g_mt[(size_t)row0 * DIM + coln]) =
                    __floats2bfloat162_rn(acc[mt][nt][0], acc[mt][nt][1]);
                *reinterpret_cast<__nv_bfloat162*>(&g_mt[(size_t)(row0 + 8) * DIM + coln]) =
                    __floats2bfloat162_rn(acc[mt][nt][2], acc[mt][nt][3]);
            }
        }
    } else {
        // fused band epilogue: per-row partial dots over this CTA's 128-col chunk.
        // dotp[r] += y[r,:].x[r+1,:]  dotm[r] += y[r,:].x[r-1,:]
        // as[r]   += x[r,:].ub[:]     bv[r]   += x[r,:].vb[:]
        const __nv_bfloat16* X = g_xbf;
        #pragma unroll
        for (int mt = 0; mt < 4; mt++) {
            #pragma unroll
            for (int h = 0; h < 2; h++) {
                int row = m0 + wm * 64 + mt * 16 + gid + h * 8;
                int rp = (row == NROWS - 1) ? row : row + 1;
                int rm = (row == 0) ? row : row - 1;
                float dp = 0.f, dm = 0.f, da = 0.f, db = 0.f;
                #pragma unroll
                for (int nt = 0; nt < 4; nt++) {
                    int col = n0 + wn * 32 + nt * 8 + tig * 2;
                    float2 xs = __bfloat1622float2(
                        *reinterpret_cast<const __nv_bfloat162*>(&X[(size_t)row * DIM + col]));
                    float2 xp = __bfloat1622float2(
                        *reinterpret_cast<const __nv_bfloat162*>(&X[(size_t)rp * DIM + col]));
                    float2 xm = __bfloat1622float2(
                        *reinterpret_cast<const __nv_bfloat162*>(&X[(size_t)rm * DIM + col]));
                    float y0 = acc[mt][nt][h * 2 + 0];
                    float y1 = acc[mt][nt][h * 2 + 1];
                    dp += y0 * xp.x + y1 * xp.y;
                    dm += y0 * xm.x + y1 * xm.y;
                    float2 ubv = *reinterpret_cast<const float2*>(&g_ub[col]);
                    float2 vbv = *reinterpret_cast<const float2*>(&g_vb[col]);
                    da += xs.x * ubv.x + xs.y * ubv.y;
                    db += xs.x * vbv.x + xs.y * vbv.y;
                }
                // reduce across the 4 tig lanes sharing this row
                #pragma unroll
                for (int o = 1; o <= 2; o <<= 1) {
                    dp += __shfl_xor_sync(0xffffffffu, dp, o);
                    dm += __shfl_xor_sync(0xffffffffu, dm, o);
                    da += __shfl_xor_sync(0xffffffffu, da, o);
                    db += __shfl_xor_sync(0xffffffffu, db, o);
                }
                if (tig == 0) {
                    atomicAdd(&g_dotp[row], dp);
                    atomicAdd(&g_dotm[row], dm);
                    atomicAdd(&g_as[row],   da);
                    atomicAdd(&g_bv[row],   db);
                }
            }
        }
    }
}

// ---------------- K4: finalize band softmax from accumulated scalars ----------------
__global__ void finalize_kernel(const int* __restrict__ eos) {
    int r = blockIdx.x * 256 + threadIdx.x;
    int b = r >> 10, s = r & 1023;
    int ep = 0, em = 0;
    if (s < SEQ - 1) ep = eos[((size_t)b * SEQ + s) * SEQ + (s + 1)];
    if (s > 0)       em = eos[((size_t)b * SEQ + s) * SEQ + (s - 1)];
    bool vp = (ep != 0), vm = (em != 0);

    float pp = 0.f, pm = 0.f;
    int mk = 0;
    if (!vp && !vm) {
        mk = 1;   // fully masked row -> uniform 1/1024 downstream
    } else {
        int rp = (r == NROWS - 1) ? r : r + 1;
        int rm = (r == 0) ? r : r - 1;
        float cd = g_cdot;
        float sp = vp ? (g_dotp[r] + g_as[r] + g_bv[rp] + cd) * INV1024 : -INFINITY;
        float sm = vm ? (g_dotm[r] + g_as[r] + g_bv[rm] + cd) * INV1024 : -INFINITY;
        float mx = fmaxf(sp, sm);
        float e1 = vp ? expf(sp - mx) : 0.f;
        float e2 = vm ? expf(sm - mx) : 0.f;
        float z = e1 + e2;
        pp = e1 / z; pm = e2 / z;
    }
    g_pp[r] = pp; g_pm[r] = pm; g_msk[r] = mk;
}

// ---------------- K5: per-batch fp64 exclusive prefix scan -> fp32 hi/lo split ----------------
__global__ void scan_kernel() {
    int b = blockIdx.x;
    int s = threadIdx.x;          // 1024 threads
    int r = b * SEQ + s;
    __shared__ double sd[SEQ];

    double logn = 0.0;
    if (s < SEQ - 1) {
        float Pp = g_msk[r]     ? INV1024 : g_pp[r];
        float Pm = g_msk[r + 1] ? INV1024 : g_pm[r + 1];
        float nb = sqrtf(Pp * Pm + 1e-9f);
        logn = (double)logf(nb + 1e-9f);
    }
    sd[s] = logn;
    __syncthreads();
    for (int off = 1; off < SEQ; off <<= 1) {
        double v = (s >= off) ? sd[s - off] : 0.0;
        __syncthreads();
        sd[s] += v;
        __syncthreads();
    }
    double c = (s == 0) ? 0.0 : sd[s - 1];
    float hi = (float)c;
    g_chi[r] = hi;
    g_clo[r] = (float)(c - (double)hi);
}

// ---------------- K6: assemble g and neibor, write both outputs (all fp32) ----------------
__global__ void out_kernel(float* __restrict__ out) {
    int b  = blockIdx.y;
    int s0 = blockIdx.x * 16;
    int tid = threadIdx.x;         // 256 threads, 4 t-values each

    __shared__ float chi_sh[SEQ];
    __shared__ float clo_sh[SEQ];
    __shared__ float pp_sh[SEQ];
    __shared__ float pm_sh[SEQ];
    __shared__ unsigned char mk_sh[SEQ];

    int base = b * SEQ;
    for (int i = tid; i < SEQ; i += 256) {
        chi_sh[i] = g_chi[base + i];
        clo_sh[i] = g_clo[base + i];
        pp_sh[i]  = g_pp[base + i];
        pm_sh[i]  = g_pm[base + i];
        mk_sh[i]  = (unsigned char)g_msk[base + i];
    }
    __syncthreads();

    float* gout = out;
    float* nout = out + (size_t)BATCH * SEQ * SEQ;
    int t0 = tid * 4;

    for (int i = 0; i < 16; i++) {
        int s = s0 + i;
        float chs = chi_sh[s], cls = clo_sh[s];
        float pps = pp_sh[s], pms = pm_sh[s];
        int ms = mk_sh[s];
        float4 gg, nn;
        float* gp = reinterpret_cast<float*>(&gg);
        float* np = reinterpret_cast<float*>(&nn);
        #pragma unroll
        for (int j = 0; j < 4; j++) {
            int t = t0 + j;
            int mt = mk_sh[t];
            float Pst = ms ? INV1024 : ((t == s + 1) ? pps : ((t == s - 1) ? pms : 0.f));
            float Pts = mt ? INV1024 : ((t == s - 1) ? pp_sh[t] : ((t == s + 1) ? pm_sh[t] : 0.f));
            float nb = sqrtf(Pst * Pts + 1e-9f);
            np[j] = nb;
            float gv;
            if (t == s) {
                gv = nb;                                   // diag: neibor[s,s]
            } else {
                float dh = (t > s) ? (chi_sh[t] - chs) : (chs - chi_sh[t]);
                float dl = (t > s) ? (clo_sh[t] - cls) : (cls - clo_sh[t]);
                gv = expf(dh + dl) + 1e-9f;                // off-diag: telescoped product
            }
            gp[j] = gv;
        }
        size_t o = ((size_t)(base + s)) * SEQ + t0;
        *reinterpret_cast<float4*>(gout + o) = gg;
        *reinterpret_cast<float4*>(nout + o) = nn;
    }
}

// ---------------- launch ----------------
extern "C" void kernel_launch(void* const* d_in, const int* in_sizes, int n_in,
                              void* d_out, int out_size) {
    const float* context = (const float*)d_in[0];
    const int*   eos     = (const int*)  d_in[1];
    const float* Wq      = (const float*)d_in[2];
    const float* bq      = (const float*)d_in[3];
    const float* Wk      = (const float*)d_in[4];
    const float* bk      = (const float*)d_in[5];
    const float* ln_a    = (const float*)d_in[6];
    const float* ln_b    = (const float*)d_in[7];
    float* out = (float*)d_out;

    cudaFuncSetAttribute(gemm_tpl<0>, cudaFuncAttributeMaxDynamicSharedMemorySize, SMEMSZ);
    cudaFuncSetAttribute(gemm_tpl<1>, cudaFuncAttributeMaxDynamicSharedMemorySize, SMEMSZ);

    ln_kernel<<<NROWS, 256>>>(context, ln_a, ln_b);
    tconv_kernel<<<dim3(32, 32, 2), 256>>>(Wq, Wk, bq, bk);
    gemm_tpl<0><<<dim3(DIM / GBN, DIM / GBM), 256, SMEMSZ>>>();      // Mt = Wk^T Wq
    gemm_tpl<1><<<dim3(DIM / GBN, NROWS / GBM), 256, SMEMSZ>>>();    // y=X*M + fused band dots
    finalize_kernel<<<NROWS / 256, 256>>>(eos);
    scan_kernel<<<BATCH, SEQ>>>();
    out_kernel<<<dim3(SEQ / 16, BATCH), 256>>>(out);
}

// round 16
// speedup vs baseline: 1.6371x; 1.0253x over previous
#include <cuda_runtime.h>
#include <cuda_bf16.h>
#include <math.h>
#include <stdint.h>

// Problem constants (B=8, S=1024, D=1024)
#define BATCH 8
#define SEQ   1024
#define DIM   1024
#define NROWS (BATCH*SEQ)     // 8192
#define INV1024 (1.0f/1024.0f)

// ---------------- scratch (__device__ globals: no allocations allowed) ----------------
__device__ __nv_bfloat16 g_xbf[(size_t)NROWS*DIM];     // layernormed X, bf16   (16 MB)
__device__ __nv_bfloat16 g_wqt[(size_t)DIM*DIM];       // Wq transposed [i][o]  (2 MB)
__device__ __nv_bfloat16 g_wkt[(size_t)DIM*DIM];       // Wk transposed [j][o]  (2 MB)
__device__ __nv_bfloat16 g_mt [(size_t)DIM*DIM];       // Mt[j][i] = (Wq^T Wk)[i][j] (2 MB)
__device__ float         g_ub[DIM];                    // Wq^T bk
__device__ float         g_vb[DIM];                    // Wk^T bq
__device__ float         g_cdot;                       // bq . bk
__device__ float         g_dotp[NROWS];                // y[r] . x[r+1]  (atomic accum)
__device__ float         g_dotm[NROWS];                // y[r] . x[r-1]
__device__ float         g_as [NROWS];                 // x[r] . ub
__device__ float         g_bv [NROWS];                 // x[r] . vb
__device__ float         g_pp[NROWS];                  // p[s,s+1]
__device__ float         g_pm[NROWS];                  // p[s,s-1]
__device__ int           g_msk[NROWS];                 // row fully masked
__device__ float         g_chi[NROWS];                 // prefix sum hi (fp32)
__device__ float         g_clo[NROWS];                 // prefix sum lo (fp32)

// ---------------- helpers ----------------
__device__ __forceinline__ void cp_async16(void* sm, const void* gm) {
    unsigned sa = (unsigned)__cvta_generic_to_shared(sm);
    asm volatile("cp.async.cg.shared.global [%0], [%1], 16;\n" :: "r"(sa), "l"(gm) : "memory");
}
#define CP_COMMIT() asm volatile("cp.async.commit_group;\n" ::)
#define CP_WAIT(n)  asm volatile("cp.async.wait_group %0;\n" :: "n"(n))

__device__ __forceinline__ void mma16816(float* c, const uint32_t* a, const uint32_t* b) {
    asm volatile(
        "mma.sync.aligned.m16n8k16.row.col.f32.bf16.bf16.f32 "
        "{%0,%1,%2,%3}, {%4,%5,%6,%7}, {%8,%9}, {%0,%1,%2,%3};\n"
        : "+f"(c[0]), "+f"(c[1]), "+f"(c[2]), "+f"(c[3])
        : "r"(a[0]), "r"(a[1]), "r"(a[2]), "r"(a[3]), "r"(b[0]), "r"(b[1]));
}

__device__ __forceinline__ void ldsm_x4(uint32_t* r, uint32_t saddr) {
    asm volatile("ldmatrix.sync.aligned.m8n8.x4.shared.b16 {%0,%1,%2,%3}, [%4];"
        : "=r"(r[0]), "=r"(r[1]), "=r"(r[2]), "=r"(r[3]) : "r"(saddr));
}

__device__ __forceinline__ uint32_t smem_u32(const void* p) {
    return (uint32_t)__cvta_generic_to_shared(p);
}

// ---------------- K1: LayerNorm (ddof=1, eps on std) -> bf16; zero accumulators ----------------
__global__ void ln_kernel(const float* __restrict__ ctx,
                          const float* __restrict__ ln_a,
                          const float* __restrict__ ln_b) {
    int r = blockIdx.x;            // 0..8191
    int tid = threadIdx.x;         // 256 threads, 4 elems each
    if (r == 0) {                  // zero all atomic accumulators (runs before tconv/gemm1)
        for (int i = tid; i < DIM; i += 256) { g_ub[i] = 0.f; g_vb[i] = 0.f; }
        for (int i = tid; i < NROWS; i += 256) {
            g_dotp[i] = 0.f; g_dotm[i] = 0.f; g_as[i] = 0.f; g_bv[i] = 0.f;
        }
        if (tid == 0) g_cdot = 0.f;
    }
    const float4* xrow = reinterpret_cast<const float4*>(ctx + (size_t)r * DIM);
    float4 v = xrow[tid];

    __shared__ float red[8];
    float s = v.x + v.y + v.z + v.w;
    #pragma unroll
    for (int o = 16; o; o >>= 1) s += __shfl_xor_sync(0xffffffffu, s, o);
    if ((tid & 31) == 0) red[tid >> 5] = s;
    __syncthreads();
    float tot = 0.f;
    #pragma unroll
    for (int i = 0; i < 8; i++) tot += red[i];
    float mean = tot * (1.0f / 1024.0f);
    __syncthreads();
    float dx0 = v.x - mean, dx1 = v.y - mean, dx2 = v.z - mean, dx3 = v.w - mean;
    float s2 = dx0*dx0 + dx1*dx1 + dx2*dx2 + dx3*dx3;
    #pragma unroll
    for (int o = 16; o; o >>= 1) s2 += __shfl_xor_sync(0xffffffffu, s2, o);
    if ((tid & 31) == 0) red[tid >> 5] = s2;
    __syncthreads();
    float tot2 = 0.f;
    #pragma unroll
    for (int i = 0; i < 8; i++) tot2 += red[i];
    float var = tot2 * (1.0f / 1023.0f);
    float rs = 1.0f / (sqrtf(var) + 1e-6f);

    float4 a4 = reinterpret_cast<const float4*>(ln_a)[tid];
    float4 b4 = reinterpret_cast<const float4*>(ln_b)[tid];
    float y0 = a4.x * (dx0 * rs) + b4.x;
    float y1 = a4.y * (dx1 * rs) + b4.y;
    float y2 = a4.z * (dx2 * rs) + b4.z;
    float y3 = a4.w * (dx3 * rs) + b4.w;

    __nv_bfloat162* orow = reinterpret_cast<__nv_bfloat162*>(g_xbf + (size_t)r * DIM);
    orow[tid*2]   = __floats2bfloat162_rn(y0, y1);
    orow[tid*2+1] = __floats2bfloat162_rn(y2, y3);
}

// ---------------- K2: transpose+convert Wq,Wk -> bf16 [in][out] + fused bias matvecs --------
__global__ void tconv_kernel(const float* __restrict__ Wq, const float* __restrict__ Wk,
                             const float* __restrict__ bq, const float* __restrict__ bk) {
    __shared__ float t[32][33];
    __shared__ float red2[8][33];
    int i0 = blockIdx.x * 32;
    int o0 = blockIdx.y * 32;
    int bz = blockIdx.z;
    const float* src = bz ? Wk : Wq;
    const float* bv  = bz ? bq : bk;
    float* dstb      = bz ? g_vb : g_ub;
    __nv_bfloat16* dst = bz ? g_wkt : g_wqt;
    int tid = threadIdx.x;
    int c = tid & 31, r = tid >> 5;   // 8 rows/iter
    #pragma unroll
    for (int rr = 0; rr < 4; rr++) {
        int row = rr * 8 + r;
        t[row][c] = src[(size_t)(o0 + row) * DIM + i0 + c];
    }
    __syncthreads();
    #pragma unroll
    for (int rr = 0; rr < 4; rr++) {
        int row = rr * 8 + r;
        dst[(size_t)(i0 + row) * DIM + o0 + c] = __float2bfloat16(t[c][row]);
    }
    float p = 0.f;
    #pragma unroll
    for (int k = 0; k < 4; k++) {
        int row = r + k * 8;
        p += t[row][c] * bv[o0 + row];
    }
    red2[r][c] = p;
    __syncthreads();
    if (r == 0) {
        float sum = 0.f;
        #pragma unroll
        for (int k = 0; k < 8; k++) sum += red2[k][c];
        atomicAdd(&dstb[i0 + c], sum);
    }
    if (bz == 0 && blockIdx.x == 0 && tid < 32) {
        float cd = bq[o0 + tid] * bk[o0 + tid];
        #pragma unroll
        for (int off = 16; off; off >>= 1) cd += __shfl_xor_sync(0xffffffffu, cd, off);
        if (tid == 0) atomicAdd(&g_cdot, cd);
    }
}

// ---------------- K3: templated 3-stage bf16 GEMM, GBK=64, ldmatrix fragments --------
#define GBM 128
#define GBN 128
#define GBK 64
#define SPAD 72
#define GSTAGES 3
#define SMEMSZ (GSTAGES * (GBM + GBN) * SPAD * 2)   // 110592 B

template <int MODE>
__global__ __launch_bounds__(256, 2) void gemm_tpl() {
    extern __shared__ __align__(16) char dynsm[];
    auto As = reinterpret_cast<__nv_bfloat16(*)[GBM][SPAD]>(dynsm);
    auto Bs = reinterpret_cast<__nv_bfloat16(*)[GBN][SPAD]>(dynsm + GSTAGES * GBM * SPAD * 2);

    const __nv_bfloat16* Ag = (MODE == 0) ? g_wkt : g_xbf;
    const __nv_bfloat16* Bg = (MODE == 0) ? g_wqt : g_mt;

    int tid  = threadIdx.x;
    int m0   = blockIdx.y * GBM;
    int n0   = blockIdx.x * GBN;
    int warp = tid >> 5, lane = tid & 31;
    int wm = warp >> 2, wn = warp & 3;      // 2 (M) x 4 (N) warps; warp tile 64x32
    int gid = lane >> 2, tig = lane & 3;
    int quad = lane >> 3, rowin = lane & 7; // ldmatrix address lanes

    float acc[4][4][4];
    #pragma unroll
    for (int a = 0; a < 4; a++)
        #pragma unroll
        for (int b = 0; b < 4; b++)
            #pragma unroll
            for (int c = 0; c < 4; c++) acc[a][b][c] = 0.f;

    auto load_stage = [&](int buf, int kt) {
        int k0 = kt * GBK;
        #pragma unroll
        for (int h = 0; h < 4; h++) {
            int chunk = tid + h * 256;       // 1024 chunks of 16B per operand
            int row = chunk >> 3;
            int cc  = chunk & 7;
            cp_async16(&As[buf][row][cc*8], Ag + (size_t)(m0 + row) * DIM + k0 + cc*8);
            cp_async16(&Bs[buf][row][cc*8], Bg + (size_t)(n0 + row) * DIM + k0 + cc*8);
        }
        CP_COMMIT();
    };

    const int NT = DIM / GBK;   // 16
    load_stage(0, 0);
    load_stage(1, 1);

    int a_row0 = wm * 64 + rowin + (quad & 1) * 8;
    int a_col0 = (quad >> 1) * 8;
    int b_row0 = wn * 32 + rowin + (quad >> 1) * 8;
    int b_col0 = (quad & 1) * 8;

    for (int kt = 0; kt < NT; kt++) {
        if (kt < NT - 1) { CP_WAIT(1); } else { CP_WAIT(0); }
        __syncthreads();
        if (kt + 2 < NT) load_stage((kt + 2) % GSTAGES, kt + 2);
        int buf = kt % GSTAGES;
        uint32_t abase = smem_u32(&As[buf][0][0]);
        uint32_t bbase = smem_u32(&Bs[buf][0][0]);

        #pragma unroll
        for (int ks = 0; ks < 4; ks++) {
            uint32_t af[4][4], bfr[4][2];
            #pragma unroll
            for (int mt = 0; mt < 4; mt++)
                ldsm_x4(af[mt], abase + ((a_row0 + mt * 16) * SPAD + ks * 16 + a_col0) * 2);
            #pragma unroll
            for (int ntp = 0; ntp < 2; ntp++)
                ldsm_x4(&bfr[ntp * 2][0], bbase + ((b_row0 + ntp * 16) * SPAD + ks * 16 + b_col0) * 2);
            #pragma unroll
            for (int mt = 0; mt < 4; mt++)
                #pragma unroll
                for (int nt = 0; nt < 4; nt++)
                    mma16816(acc[mt][nt], af[mt], bfr[nt]);
        }
    }

    if (MODE == 0) {
        #pragma unroll
        for (int mt = 0; mt < 4; mt++) {
            int row0 = m0 + wm * 64 + mt * 16 + gid;
            #pragma unroll
            for (int nt = 0; nt < 4; nt++) {
                int coln = n0 + wn * 32 + nt * 8 + tig * 2;
                *reinterpret_cast<__nv_bfloat162*>(&g_mt[(size_t)row0 * DIM + coln]) =
                    __floats2bfloat162_rn(acc[mt][nt][0], acc[mt][nt][1]);
                *reinterpret_cast<__nv_bfloat162*>(&g_mt[(size_t)(row0 + 8) * DIM + coln]) =
                    __floats2bfloat162_rn(acc[mt][nt][2], acc[mt][nt][3]);
            }
        }
    } else {
        // fused band epilogue: per-row partial dots over this CTA's 128-col chunk.
        const __nv_bfloat16* X = g_xbf;
        #pragma unroll
        for (int mt = 0; mt < 4; mt++) {
            #pragma unroll
            for (int h = 0; h < 2; h++) {
                int row = m0 + wm * 64 + mt * 16 + gid + h * 8;
                int rp = (row == NROWS - 1) ? row : row + 1;
                int rm = (row == 0) ? row : row - 1;
                float dp = 0.f, dm = 0.f, da = 0.f, db = 0.f;
                #pragma unroll
                for (int nt = 0; nt < 4; nt++) {
                    int col = n0 + wn * 32 + nt * 8 + tig * 2;
                    float2 xs = __bfloat1622float2(
                        *reinterpret_cast<const __nv_bfloat162*>(&X[(size_t)row * DIM + col]));
                    float2 xp = __bfloat1622float2(
                        *reinterpret_cast<const __nv_bfloat162*>(&X[(size_t)rp * DIM + col]));
                    float2 xm = __bfloat1622float2(
                        *reinterpret_cast<const __nv_bfloat162*>(&X[(size_t)rm * DIM + col]));
                    float y0 = acc[mt][nt][h * 2 + 0];
                    float y1 = acc[mt][nt][h * 2 + 1];
                    dp += y0 * xp.x + y1 * xp.y;
                    dm += y0 * xm.x + y1 * xm.y;
                    float2 ubv = *reinterpret_cast<const float2*>(&g_ub[col]);
                    float2 vbv = *reinterpret_cast<const float2*>(&g_vb[col]);
                    da += xs.x * ubv.x + xs.y * ubv.y;
                    db += xs.x * vbv.x + xs.y * vbv.y;
                }
                #pragma unroll
                for (int o = 1; o <= 2; o <<= 1) {
                    dp += __shfl_xor_sync(0xffffffffu, dp, o);
                    dm += __shfl_xor_sync(0xffffffffu, dm, o);
                    da += __shfl_xor_sync(0xffffffffu, da, o);
                    db += __shfl_xor_sync(0xffffffffu, db, o);
                }
                if (tig == 0) {
                    atomicAdd(&g_dotp[row], dp);
                    atomicAdd(&g_dotm[row], dm);
                    atomicAdd(&g_as[row],   da);
                    atomicAdd(&g_bv[row],   db);
                }
            }
        }
    }
}

// ---------------- K4: fused finalize (softmax) + per-batch fp64 scan -> fp32 hi/lo ----------------
__global__ void scan_kernel(const int* __restrict__ eos) {
    int b = blockIdx.x;
    int s = threadIdx.x;          // 1024 threads
    int r = b * SEQ + s;

    // ---- finalize: band softmax for row r ----
    int ep = 0, em = 0;
    if (s < SEQ - 1) ep = eos[((size_t)b * SEQ + s) * SEQ + (s + 1)];
    if (s > 0)       em = eos[((size_t)b * SEQ + s) * SEQ + (s - 1)];
    bool vp = (ep != 0), vm = (em != 0);

    float pp = 0.f, pm = 0.f;
    int mk = 0;
    if (!vp && !vm) {
        mk = 1;   // fully masked row -> uniform 1/1024 downstream (ALL t, not just band)
    } else {
        int rp = (r == NROWS - 1) ? r : r + 1;
        int rm = (r == 0) ? r : r - 1;
        float cd = g_cdot;
        float sp = vp ? (g_dotp[r] + g_as[r] + g_bv[rp] + cd) * INV1024 : -INFINITY;
        float sm = vm ? (g_dotm[r] + g_as[r] + g_bv[rm] + cd) * INV1024 : -INFINITY;
        float mx = fmaxf(sp, sm);
        float e1 = vp ? expf(sp - mx) : 0.f;
        float e2 = vm ? expf(sm - mx) : 0.f;
        float z = e1 + e2;
        pp = e1 / z; pm = e2 / z;
    }
    g_pp[r] = pp; g_pm[r] = pm; g_msk[r] = mk;

    __shared__ float         sh_pm[SEQ];
    __shared__ unsigned char sh_mk[SEQ];
    __shared__ double        sd[SEQ];
    sh_pm[s] = pm; sh_mk[s] = (unsigned char)mk;
    __syncthreads();

    // ---- fp64 exclusive prefix scan of log(neibor band) ----
    double logn = 0.0;
    if (s < SEQ - 1) {
        float Pp = mk          ? INV1024 : pp;
        float Pm = sh_mk[s+1]  ? INV1024 : sh_pm[s+1];
        float nb = sqrtf(Pp * Pm + 1e-9f);
        logn = (double)logf(nb + 1e-9f);
    }
    sd[s] = logn;
    __syncthreads();
    for (int off = 1; off < SEQ; off <<= 1) {
        double v = (s >= off) ? sd[s - off] : 0.0;
        __syncthreads();
        sd[s] += v;
        __syncthreads();
    }
    double c = (s == 0) ? 0.0 : sd[s - 1];
    float hi = (float)c;
    g_chi[r] = hi;
    g_clo[r] = (float)(c - (double)hi);
}

// ---------------- K5: assemble g and neibor; MUFU only where values are live ----------------
__global__ void out_kernel(float* __restrict__ out) {
    int b  = blockIdx.y;
    int s0 = blockIdx.x * 16;
    int tid = threadIdx.x;         // 256 threads, 4 t-values each

    __shared__ float chi_sh[SEQ];
    __shared__ float clo_sh[SEQ];
    __shared__ float pp_sh[SEQ];
    __shared__ float pm_sh[SEQ];
    __shared__ unsigned char mk_sh[SEQ];

    int base = b * SEQ;
    for (int i = tid; i < SEQ; i += 256) {
        chi_sh[i] = g_chi[base + i];
        clo_sh[i] = g_clo[base + i];
        pp_sh[i]  = g_pp[base + i];
        pm_sh[i]  = g_pm[base + i];
        mk_sh[i]  = (unsigned char)g_msk[base + i];
    }
    __syncthreads();

    const float SQEPS = sqrtf(1e-9f);                          // off-band, product == 0
    const float MKMK  = sqrtf(INV1024 * INV1024 + 1e-9f);      // off-band, both rows masked
    float* gout = out;
    float* nout = out + (size_t)BATCH * SEQ * SEQ;
    int t0 = tid * 4;

    for (int i = 0; i < 16; i++) {
        int s = s0 + i;
        float chs = chi_sh[s], cls = clo_sh[s];
        float pps = pp_sh[s], pms = pm_sh[s];
        int ms = mk_sh[s];
        float4 gg, nn;
        float* gp = reinterpret_cast<float*>(&gg);
        float* np = reinterpret_cast<float*>(&nn);
        #pragma unroll
        for (int j = 0; j < 4; j++) {
            int t = t0 + j;
            float nb;
            if (t >= s - 1 && t <= s + 1) {      // band: real sqrt (3 per row)
                int mt = mk_sh[t];
                float Pst = ms ? INV1024 : ((t == s + 1) ? pps : ((t == s - 1) ? pms : 0.f));
                float Pts = mt ? INV1024 : ((t == s - 1) ? pp_sh[t] : ((t == s + 1) ? pm_sh[t] : 0.f));
                nb = sqrtf(Pst * Pts + 1e-9f);
            } else {
                // off-band: P(s,t)*P(t,s) = (ms?1/1024:0) * (mt?1/1024:0)
                nb = (ms && mk_sh[t]) ? MKMK : SQEPS;
            }
            np[j] = nb;
            float gv;
            if (t == s) {
                gv = nb;                         // diag: neibor[s,s]
            } else {
                float dh = (t > s) ? (chi_sh[t] - chs) : (chs - chi_sh[t]);
                float dl = (t > s) ? (clo_sh[t] - cls) : (cls - clo_sh[t]);
                float d = dh + dl;
                if (d > -30.f) {                 // live region: ~few % of elements
                    gv = __expf(d) + 1e-9f;
                } else {                         // exp(d) < 9.4e-14 << 1e-9 floor
                    gv = 1e-9f;
                }
            }
            gp[j] = gv;
        }
        size_t o = ((size_t)(base + s)) * SEQ + t0;
        *reinterpret_cast<float4*>(gout + o) = gg;
        *reinterpret_cast<float4*>(nout + o) = nn;
    }
}

// ---------------- launch ----------------
extern "C" void kernel_launch(void* const* d_in, const int* in_sizes, int n_in,
                              void* d_out, int out_size) {
    const float* context = (const float*)d_in[0];
    const int*   eos     = (const int*)  d_in[1];
    const float* Wq      = (const float*)d_in[2];
    const float* bq      = (const float*)d_in[3];
    const float* Wk      = (const float*)d_in[4];
    const float* bk      = (const float*)d_in[5];
    const float* ln_a    = (const float*)d_in[6];
    const float* ln_b    = (const float*)d_in[7];
    float* out = (float*)d_out;

    cudaFuncSetAttribute(gemm_tpl<0>, cudaFuncAttributeMaxDynamicSharedMemorySize, SMEMSZ);
    cudaFuncSetAttribute(gemm_tpl<1>, cudaFuncAttributeMaxDynamicSharedMemorySize, SMEMSZ);

    ln_kernel<<<NROWS, 256>>>(context, ln_a, ln_b);
    tconv_kernel<<<dim3(32, 32, 2), 256>>>(Wq, Wk, bq, bk);
    gemm_tpl<0><<<dim3(DIM / GBN, DIM / GBM), 256, SMEMSZ>>>();      // Mt = Wk^T Wq
    gemm_tpl<1><<<dim3(DIM / GBN, NROWS / GBM), 256, SMEMSZ>>>();    // y=X*M + fused band dots
    scan_kernel<<<BATCH, SEQ>>>(eos);                                // finalize + scan fused
    out_kernel<<<dim3(SEQ / 16, BATCH), 256>>>(out);
}